// round 10
// baseline (speedup 1.0000x reference)
#include <cuda_runtime.h>
#include <cuda_fp16.h>
#include <cstdint>

// ---------------- problem constants ----------------
#define B_   2
#define N_   2048
#define E_   1024
#define H_   16
#define D_   64
#define SCALE_ 0.125f     // 64^-0.5
#define RS_   4.8828125e-4f   // 2^-11 descale for residuals (stored x2048)

// ---------------- device scratch (no allocs allowed) ----------------
__device__ __half g_x_hi[(size_t)B_*N_*E_];            // x rounded
__device__ __half g_w_hi[(size_t)3*E_*E_];
__device__ __half g_w_lo[(size_t)3*E_*E_];             // residual x2048
__device__ __half g_ow_hi[(size_t)E_*E_];
__device__ __half g_ow_lo[(size_t)E_*E_];              // residual x2048
__device__ __half g_qh[(size_t)B_*H_*N_*D_];           // pre-scaled by SCALE_
__device__ __half g_ql[(size_t)B_*H_*N_*D_];           // residual x2048
__device__ __half g_kh[(size_t)B_*H_*N_*D_];
__device__ __half g_kl[(size_t)B_*H_*N_*D_];           // residual x2048
__device__ __half g_vh[(size_t)B_*H_*N_*D_];
__device__ __half g_vl[(size_t)B_*H_*N_*D_];           // residual x2048
__device__ __half g_at_hi[(size_t)B_*N_*E_];           // attention out rounded

// =====================================================================
// helpers
// =====================================================================
__device__ __forceinline__ uint32_t smem_u32(const void* p) {
    uint32_t a;
    asm("{ .reg .u64 t; cvta.to.shared.u64 t, %1; cvt.u32.u64 %0, t; }" : "=r"(a) : "l"(p));
    return a;
}
__device__ __forceinline__ uint32_t sw128(uint32_t off) { return off ^ ((off >> 3) & 0x70); }

__device__ __forceinline__ void cpa16(uint32_t dst, const void* src) {
    asm volatile("cp.async.cg.shared.global [%0], [%1], 16;" :: "r"(dst), "l"(src));
}
#define CPC() asm volatile("cp.async.commit_group;" ::: "memory")
#define CPW(n) asm volatile("cp.async.wait_group %0;" :: "n"(n) : "memory")

__device__ __forceinline__ void ldsm4(uint32_t addr, uint32_t* r) {
    asm volatile("ldmatrix.sync.aligned.m8n8.x4.shared.b16 {%0,%1,%2,%3}, [%4];"
        : "=r"(r[0]), "=r"(r[1]), "=r"(r[2]), "=r"(r[3]) : "r"(addr));
}
__device__ __forceinline__ void ldsm4t(uint32_t addr, uint32_t* r) {
    asm volatile("ldmatrix.sync.aligned.m8n8.x4.trans.shared.b16 {%0,%1,%2,%3}, [%4];"
        : "=r"(r[0]), "=r"(r[1]), "=r"(r[2]), "=r"(r[3]) : "r"(addr));
}
// fp16 in, fp32 accumulate
__device__ __forceinline__ void mma16816(float* c, const uint32_t* a, uint32_t b0, uint32_t b1) {
    asm("mma.sync.aligned.m16n8k16.row.col.f32.f16.f16.f32 "
        "{%0,%1,%2,%3},{%4,%5,%6,%7},{%8,%9},{%0,%1,%2,%3};"
        : "+f"(c[0]), "+f"(c[1]), "+f"(c[2]), "+f"(c[3])
        : "r"(a[0]), "r"(a[1]), "r"(a[2]), "r"(a[3]), "r"(b0), "r"(b1));
}
// fp16 in, fp16 accumulate (correction terms; possibly 2x rate)
__device__ __forceinline__ void mma16816h(uint32_t* c, const uint32_t* a, uint32_t b0, uint32_t b1) {
    asm("mma.sync.aligned.m16n8k16.row.col.f16.f16.f16.f16 "
        "{%0,%1},{%2,%3,%4,%5},{%6,%7},{%0,%1};"
        : "+r"(c[0]), "+r"(c[1])
        : "r"(a[0]), "r"(a[1]), "r"(a[2]), "r"(a[3]), "r"(b0), "r"(b1));
}

__device__ __forceinline__ uint32_t pack_h2(float v0, float v1) {
    __half2 h = __floats2half2_rn(v0, v1);
    return *(uint32_t*)&h;
}
// residual x2048 (exact power-of-2 scale into prime fp16 range)
__device__ __forceinline__ uint32_t pack_l2(float v0, float v1) {
    __half h0 = __float2half_rn(v0), h1 = __float2half_rn(v1);
    __half2 l = __halves2half2(__float2half_rn((v0 - __half2float(h0)) * 2048.0f),
                               __float2half_rn((v1 - __half2float(h1)) * 2048.0f));
    return *(uint32_t*)&l;
}
__device__ __forceinline__ float lo_f(uint32_t u) { return __low2float(*(__half2*)&u); }
__device__ __forceinline__ float hi_f(uint32_t u) { return __high2float(*(__half2*)&u); }

// =====================================================================
// split kernels
// W=0: x -> hi only.  W=1: qkv_w -> hi/lo.  W=2: out_w -> hi/lo.
// =====================================================================
template<int W>
__global__ void split_kernel(const float* __restrict__ src, int n4)
{
    int i = blockIdx.x * blockDim.x + threadIdx.x;
    if (i >= n4) return;
    float4 a = *(const float4*)&src[(size_t)i * 4];
    uint2 hv = {pack_h2(a.x, a.y), pack_h2(a.z, a.w)};
    if (W == 0) {
        *(uint2*)&g_x_hi[(size_t)i * 4] = hv;
    } else {
        __half* hi = (W == 1) ? g_w_hi : g_ow_hi;
        __half* lo = (W == 1) ? g_w_lo : g_ow_lo;
        uint2 lv = {pack_l2(a.x, a.y), pack_l2(a.z, a.w)};
        *(uint2*)&hi[(size_t)i * 4] = hv;
        *(uint2*)&lo[(size_t)i * 4] = lv;
    }
}

// =====================================================================
// mma.sync GEMM (NT), fp16: main = A*Bh (fp32 acc), corr = A*Bl_s (fp16 acc).
// BM=128, BN=128, BK=64. 256 threads, 8 warps (2x4), warp tile 64x32.
// smem stage: Ah(16K)+Bh(16K)+Bl(16K)=48KB, double buffered.
// MODE 0: epilogue -> q/k/v hi/lo (scatter [B,H,N,D], q scaled); MODE 1: fp32 C.
// =====================================================================
#define GQ_TILE 16384                // 128 rows * 128B
#define GQ_STAGE (3 * GQ_TILE)       // 48KB

extern __shared__ __align__(16) char dyn_smem[];

template<int MODE>
__global__ __launch_bounds__(256, 1)
void gemm_mma(const float* __restrict__ bias, float* __restrict__ C, int K, int Nout)
{
    const __half* Ah = (MODE == 0) ? g_x_hi : g_at_hi;
    const __half* Bh = (MODE == 0) ? g_w_hi : g_ow_hi;
    const __half* Bl = (MODE == 0) ? g_w_lo : g_ow_lo;

    char* sm = (char*)(((uintptr_t)dyn_smem + 1023) & ~(uintptr_t)1023);
    uint32_t sb = smem_u32(sm);

    int tid = threadIdx.x;
    int lane = tid & 31;
    int wid = tid >> 5;              // 0..7
    int wm = wid >> 2;               // 0..1 -> rows wm*64
    int wn = wid & 3;                // 0..3 -> cols wn*32
    int m0 = blockIdx.y * 128;
    int n0 = blockIdx.x * 128;

    float acc[4][4][4];
    uint32_t accL[4][4][2];
#pragma unroll
    for (int a = 0; a < 4; a++)
#pragma unroll
        for (int b = 0; b < 4; b++) {
#pragma unroll
            for (int c = 0; c < 4; c++) acc[a][b][c] = 0.f;
            accL[a][b][0] = 0u; accL[a][b][1] = 0u;
        }

    // quarter q of stage loads: 3 cpa16/thread
    auto load_quarter = [&](int s, int k0, int q) {
        uint32_t st = sb + s * GQ_STAGE;
        int idx = tid + q * 256;            // 0..1023
        int row = idx >> 3, seg = idx & 7;
        uint32_t off = sw128((uint32_t)(row * 128 + seg * 16));
        size_t goA = (size_t)(m0 + row) * K + k0 + seg * 8;
        size_t goB = (size_t)(n0 + row) * K + k0 + seg * 8;
        cpa16(st + off, Ah + goA);
        cpa16(st + GQ_TILE + off, Bh + goB);
        cpa16(st + 2 * GQ_TILE + off, Bl + goB);
    };

    const int NIT = K / 64;
#pragma unroll
    for (int q = 0; q < 4; q++) load_quarter(0, 0, q);
    CPC();

    for (int it = 0; it < NIT; it++) {
        int s = it & 1;
        CPW(0);
        __syncthreads();

        uint32_t aH = sb + s * GQ_STAGE;
        uint32_t bHs = aH + GQ_TILE;
        uint32_t bLs = aH + 2 * GQ_TILE;
        bool pre = (it + 1 < NIT);

#pragma unroll
        for (int ks = 0; ks < 4; ks++) {
            if (pre) load_quarter(s ^ 1, (it + 1) * 64, ks);

            int koff = (ks * 16 + (lane >> 4) * 8) * 2;
            uint32_t ah[4][4];
#pragma unroll
            for (int tm = 0; tm < 4; tm++) {
                int ar = wm * 64 + tm * 16 + (lane & 15);
                uint32_t off = sw128((uint32_t)(ar * 128 + koff));
                ldsm4(aH + off, ah[tm]);
            }
#pragma unroll
            for (int u = 0; u < 2; u++) {
                int br = wn * 32 + u * 16 + (lane & 15);
                uint32_t off = sw128((uint32_t)(br * 128 + koff));
                uint32_t bh[4], bl[4];
                ldsm4(bHs + off, bh);
                ldsm4(bLs + off, bl);
#pragma unroll
                for (int tm = 0; tm < 4; tm++) {
                    mma16816(acc[tm][2*u],   ah[tm], bh[0], bh[2]);
                    mma16816(acc[tm][2*u+1], ah[tm], bh[1], bh[3]);
                }
#pragma unroll
                for (int tm = 0; tm < 4; tm++) {
                    mma16816h(accL[tm][2*u],   ah[tm], bl[0], bl[2]);
                    mma16816h(accL[tm][2*u+1], ah[tm], bl[1], bl[3]);
                }
            }
        }
        if (pre) CPC();
    }

    // ---- epilogue: merge fp16 corrections (x 2^-11), add bias, store ----
#pragma unroll
    for (int tm = 0; tm < 4; tm++) {
#pragma unroll
        for (int j = 0; j < 4; j++) {
            int nb = n0 + wn * 32 + j * 8 + (lane & 3) * 2;
            float2 bv = *(const float2*)&bias[nb];
#pragma unroll
            for (int half = 0; half < 2; half++) {
                int m = m0 + wm * 64 + tm * 16 + (lane >> 2) + half * 8;
                uint32_t cr = accL[tm][j][half];
                float v0 = acc[tm][j][half * 2 + 0] + RS_ * lo_f(cr) + bv.x;
                float v1 = acc[tm][j][half * 2 + 1] + RS_ * hi_f(cr) + bv.y;
                if (MODE == 0) {
                    int bb = m >> 11, nn = m & (N_ - 1);
                    int which = nb >> 10, e = nb & 1023;
                    int h = e >> 6, d = e & 63;
                    if (which == 0) { v0 *= SCALE_; v1 *= SCALE_; }
                    __half* dh = (which == 0) ? g_qh : (which == 1) ? g_kh : g_vh;
                    __half* dl = (which == 0) ? g_ql : (which == 1) ? g_kl : g_vl;
                    size_t idx = (((size_t)bb * H_ + h) * N_ + nn) * D_ + d;
                    *(uint32_t*)&dh[idx] = pack_h2(v0, v1);
                    *(uint32_t*)&dl[idx] = pack_l2(v0, v1);
                } else {
                    float2 v = {v0, v1};
                    *(float2*)&C[(size_t)m * Nout + nb] = v;
                }
            }
        }
    }
}

// =====================================================================
// Flash attention, fp16:
//   S  = qh*kh (fp32 acc) + [qh*kl_s + ql_s*kh] (fp16 acc, x 2^-11)
//   O += Ph*Vh (fp32 acc) + Ph*Vl_s (fp16 acc, merged per iter)
// Block = 128 threads (4 warps), q-tile 64 rows, D=64.
// =====================================================================
#define AKV_STAGE 32768
#define ATT_SMEM (1024 + 16384 + 2 * AKV_STAGE)

__global__ __launch_bounds__(128, 2)
void attention_kernel()
{
    char* sm = (char*)(((uintptr_t)dyn_smem + 1023) & ~(uintptr_t)1023);
    uint32_t sb = smem_u32(sm);
    const uint32_t Pha = sb;           // P hi (mainloop) / Q hi (prologue)
    const uint32_t Qla = sb + 8192;    // Q lo (prologue only)
    const uint32_t KVb = sb + 16384;   // stage s: Kh, Kl, Vh, Vl (8KB each)

    int tid = threadIdx.x;
    int lane = tid & 31;
    int wid = tid >> 5;
    int qt = gridDim.x - 1 - blockIdx.x;   // heavy tiles first
    int bh = blockIdx.y;
    size_t base = (size_t)bh * N_ * D_;

#pragma unroll
    for (int l = 0; l < 4; l++) {
        int idx = tid + l * 128;
        int row = idx >> 3, seg = idx & 7;
        size_t go = base + (size_t)(qt * 64 + row) * D_ + seg * 8;
        uint32_t off = sw128((uint32_t)(row * 128 + seg * 16));
        cpa16(Pha + off, g_qh + go);
        cpa16(Qla + off, g_ql + go);
    }
    CPC();

    auto load_kv = [&](int s, int kt) {
        uint32_t kvb = KVb + s * AKV_STAGE;
#pragma unroll
        for (int l = 0; l < 4; l++) {
            int idx = tid + l * 128;
            int row = idx >> 3, seg = idx & 7;
            size_t go = base + (size_t)(kt * 64 + row) * D_ + seg * 8;
            uint32_t off = sw128((uint32_t)(row * 128 + seg * 16));
            cpa16(kvb + off, g_kh + go);
            cpa16(kvb + 8192 + off, g_kl + go);
            cpa16(kvb + 16384 + off, g_vh + go);
            cpa16(kvb + 24576 + off, g_vl + go);
        }
        CPC();
    };
    load_kv(0, 0);

    CPW(0);
    __syncthreads();

    uint32_t qh[4][4], qlr[4][4];
    int ar = wid * 16 + (lane & 15);
#pragma unroll
    for (int ks = 0; ks < 4; ks++) {
        uint32_t off = sw128((uint32_t)(ar * 128 + (ks * 16 + (lane >> 4) * 8) * 2));
        ldsm4(Pha + off, qh[ks]);
        ldsm4(Qla + off, qlr[ks]);
    }

    float o[8][4];
#pragma unroll
    for (int j = 0; j < 8; j++)
#pragma unroll
        for (int e = 0; e < 4; e++) o[j][e] = 0.f;
    float m0r = -1e30f, m1r = -1e30f, l0 = 0.f, l1 = 0.f;

    int rowl0 = wid * 16 + (lane >> 2);
    int rowl1 = rowl0 + 8;

    for (int kt = 0; kt <= qt; kt++) {
        int s = kt & 1;
        __syncthreads();
        if (kt < qt) load_kv(s ^ 1, kt + 1);
        if (kt < qt) { CPW(1); } else { CPW(0); }
        __syncthreads();

        uint32_t Kh = KVb + s * AKV_STAGE;
        uint32_t Kl = Kh + 8192;
        uint32_t Vh = Kh + 16384;
        uint32_t Vl = Kh + 24576;

        // ---- S main (fp32) + corrections (fp16) ----
        float sc[8][4];
        uint32_t scC[8][2];
#pragma unroll
        for (int j = 0; j < 8; j++) {
#pragma unroll
            for (int e = 0; e < 4; e++) sc[j][e] = 0.f;
            scC[j][0] = 0u; scC[j][1] = 0u;
        }

#pragma unroll
        for (int ks = 0; ks < 4; ks++) {
            int koff = (ks * 16 + (lane >> 4) * 8) * 2;
            uint32_t kh4[4][4], kl4[4][4];
#pragma unroll
            for (int u = 0; u < 4; u++) {
                int br = u * 16 + (lane & 15);
                uint32_t off = sw128((uint32_t)(br * 128 + koff));
                ldsm4(Kh + off, kh4[u]);
                ldsm4(Kl + off, kl4[u]);
            }
#pragma unroll
            for (int u = 0; u < 4; u++) {
                mma16816(sc[2*u],   qh[ks], kh4[u][0], kh4[u][2]);
                mma16816(sc[2*u+1], qh[ks], kh4[u][1], kh4[u][3]);
            }
#pragma unroll
            for (int u = 0; u < 4; u++) {
                mma16816h(scC[2*u],   qh[ks], kl4[u][0], kl4[u][2]);
                mma16816h(scC[2*u+1], qh[ks], kl4[u][1], kl4[u][3]);
            }
#pragma unroll
            for (int u = 0; u < 4; u++) {
                mma16816h(scC[2*u],   qlr[ks], kh4[u][0], kh4[u][2]);
                mma16816h(scC[2*u+1], qlr[ks], kh4[u][1], kh4[u][3]);
            }
        }
        // merge corrections
#pragma unroll
        for (int j = 0; j < 8; j++) {
            sc[j][0] += RS_ * lo_f(scC[j][0]);
            sc[j][1] += RS_ * hi_f(scC[j][0]);
            sc[j][2] += RS_ * lo_f(scC[j][1]);
            sc[j][3] += RS_ * hi_f(scC[j][1]);
        }

        if (kt == qt) {
#pragma unroll
            for (int j = 0; j < 8; j++) {
                int c = j * 8 + (lane & 3) * 2;
                if (c     > rowl0) sc[j][0] = -1e30f;
                if (c + 1 > rowl0) sc[j][1] = -1e30f;
                if (c     > rowl1) sc[j][2] = -1e30f;
                if (c + 1 > rowl1) sc[j][3] = -1e30f;
            }
        }

        // ---- online softmax ----
        float t0 = -1e30f, t1 = -1e30f;
#pragma unroll
        for (int j = 0; j < 8; j++) {
            t0 = fmaxf(t0, fmaxf(sc[j][0], sc[j][1]));
            t1 = fmaxf(t1, fmaxf(sc[j][2], sc[j][3]));
        }
        t0 = fmaxf(t0, __shfl_xor_sync(0xffffffff, t0, 1));
        t0 = fmaxf(t0, __shfl_xor_sync(0xffffffff, t0, 2));
        t1 = fmaxf(t1, __shfl_xor_sync(0xffffffff, t1, 1));
        t1 = fmaxf(t1, __shfl_xor_sync(0xffffffff, t1, 2));
        float nm0 = fmaxf(m0r, t0), nm1 = fmaxf(m1r, t1);
        float f0 = __expf(m0r - nm0), f1 = __expf(m1r - nm1);
        m0r = nm0; m1r = nm1;

        float s0 = 0.f, s1 = 0.f;
#pragma unroll
        for (int j = 0; j < 8; j++) {
            float p0 = __expf(sc[j][0] - nm0);
            float p1 = __expf(sc[j][1] - nm0);
            float p2 = __expf(sc[j][2] - nm1);
            float p3 = __expf(sc[j][3] - nm1);
            s0 += p0 + p1; s1 += p2 + p3;
            uint32_t coff = (uint32_t)(j * 16 + (lane & 3) * 4);
            uint32_t off0 = sw128((uint32_t)(rowl0 * 128) + coff);
            uint32_t off1 = sw128((uint32_t)(rowl1 * 128) + coff);
            *(uint32_t*)(sm + off0) = pack_h2(p0, p1);
            *(uint32_t*)(sm + off1) = pack_h2(p2, p3);
            o[j][0] *= f0; o[j][1] *= f0; o[j][2] *= f1; o[j][3] *= f1;
        }
        s0 += __shfl_xor_sync(0xffffffff, s0, 1);
        s0 += __shfl_xor_sync(0xffffffff, s0, 2);
        s1 += __shfl_xor_sync(0xffffffff, s1, 1);
        s1 += __shfl_xor_sync(0xffffffff, s1, 2);
        l0 = l0 * f0 + s0;
        l1 = l1 * f1 + s1;
        __syncwarp();

        // ---- O += P V: main (fp32) + P*Vl_s (fp16, per-iter) ----
        uint32_t oc[8][2];
#pragma unroll
        for (int j = 0; j < 8; j++) { oc[j][0] = 0u; oc[j][1] = 0u; }

#pragma unroll
        for (int ks = 0; ks < 4; ks++) {
            uint32_t offp = sw128((uint32_t)(ar * 128 + (ks * 16 + (lane >> 4) * 8) * 2));
            uint32_t ph4[4];
            ldsm4(Pha + offp, ph4);
            uint32_t vh4[4][4], vl4[4][4];
#pragma unroll
            for (int u = 0; u < 4; u++) {
                int vr = ks * 16 + ((lane >> 4) << 3) + (lane & 7);
                int vc = u * 16 + ((lane >> 3) & 1) * 8;
                uint32_t offv = sw128((uint32_t)(vr * 128 + vc * 2));
                ldsm4t(Vh + offv, vh4[u]);
                ldsm4t(Vl + offv, vl4[u]);
            }
#pragma unroll
            for (int u = 0; u < 4; u++) {
                mma16816(o[2*u],   ph4, vh4[u][0], vh4[u][2]);
                mma16816(o[2*u+1], ph4, vh4[u][1], vh4[u][3]);
            }
#pragma unroll
            for (int u = 0; u < 4; u++) {
                mma16816h(oc[2*u],   ph4, vl4[u][0], vl4[u][2]);
                mma16816h(oc[2*u+1], ph4, vl4[u][1], vl4[u][3]);
            }
        }
        // merge per-iter corrections into fp32 O
#pragma unroll
        for (int j = 0; j < 8; j++) {
            o[j][0] += RS_ * lo_f(oc[j][0]);
            o[j][1] += RS_ * hi_f(oc[j][0]);
            o[j][2] += RS_ * lo_f(oc[j][1]);
            o[j][3] += RS_ * hi_f(oc[j][1]);
        }
    }

    // ---- epilogue: normalize + write fp16 hi [B,N,E] ----
    float inv0 = 1.f / l0, inv1 = 1.f / l1;
    int b = bh >> 4, h = bh & 15;
    int n0g = qt * 64 + rowl0;
#pragma unroll
    for (int j = 0; j < 8; j++) {
        int d = h * 64 + j * 8 + (lane & 3) * 2;
        size_t i0 = ((size_t)b * N_ + n0g) * E_ + d;
        size_t i1 = ((size_t)b * N_ + n0g + 8) * E_ + d;
        *(uint32_t*)&g_at_hi[i0] = pack_h2(o[j][0] * inv0, o[j][1] * inv0);
        *(uint32_t*)&g_at_hi[i1] = pack_h2(o[j][2] * inv1, o[j][3] * inv1);
    }
}

// =====================================================================
// launch
// =====================================================================
extern "C" void kernel_launch(void* const* d_in, const int* in_sizes, int n_in,
                              void* d_out, int out_size)
{
    const float* x     = (const float*)d_in[0];
    const float* qkv_w = (const float*)d_in[1];
    const float* qkv_b = (const float*)d_in[2];
    const float* out_w = (const float*)d_in[3];
    const float* out_b = (const float*)d_in[4];
    float* out = (float*)d_out;

    const int M = B_ * N_;
    const int gemm_smem = 2 * GQ_STAGE + 1024;   // 97 KB

    cudaFuncSetAttribute(gemm_mma<0>, cudaFuncAttributeMaxDynamicSharedMemorySize, gemm_smem);
    cudaFuncSetAttribute(gemm_mma<1>, cudaFuncAttributeMaxDynamicSharedMemorySize, gemm_smem);
    cudaFuncSetAttribute(attention_kernel, cudaFuncAttributeMaxDynamicSharedMemorySize, ATT_SMEM);

    split_kernel<0><<<(M * E_ / 4 + 255) / 256, 256>>>(x, M * E_ / 4);
    split_kernel<1><<<(3 * E_ * E_ / 4 + 255) / 256, 256>>>(qkv_w, 3 * E_ * E_ / 4);
    split_kernel<2><<<(E_ * E_ / 4 + 255) / 256, 256>>>(out_w, E_ * E_ / 4);

    gemm_mma<0><<<dim3(3 * E_ / 128, M / 128), 256, gemm_smem>>>(qkv_b, nullptr, E_, 3 * E_);

    attention_kernel<<<dim3(N_ / 64, B_ * H_), 128, ATT_SMEM>>>();

    gemm_mma<1><<<dim3(E_ / 128, M / 128), 256, gemm_smem>>>(out_b, out, E_, E_);
}

// round 11
// speedup vs baseline: 1.1726x; 1.1726x over previous
#include <cuda_runtime.h>
#include <cuda_fp16.h>
#include <cstdint>

// ---------------- problem constants ----------------
#define B_   2
#define N_   2048
#define E_   1024
#define H_   16
#define D_   64
#define SCALE_ 0.125f   // 64^-0.5

// ---------------- device scratch (no allocs allowed) ----------------
__device__ __half g_x_hi[(size_t)B_*N_*E_];            // x rounded
__device__ __half g_w_hi[(size_t)3*E_*E_];
__device__ __half g_w_lo[(size_t)3*E_*E_];             // residual
__device__ __half g_ow_hi[(size_t)E_*E_];
__device__ __half g_ow_lo[(size_t)E_*E_];              // residual
__device__ __half g_qh[(size_t)B_*H_*N_*D_];           // rounded, pre-scaled by SCALE_
__device__ __half g_kh[(size_t)B_*H_*N_*D_];
__device__ __half g_kl[(size_t)B_*H_*N_*D_];           // residual (S 2-term)
__device__ __half g_vh[(size_t)B_*H_*N_*D_];           // rounded (PV 1-term)
__device__ __half g_at_hi[(size_t)B_*N_*E_];           // attention out rounded

// =====================================================================
// helpers
// =====================================================================
__device__ __forceinline__ uint32_t smem_u32(const void* p) {
    uint32_t a;
    asm("{ .reg .u64 t; cvta.to.shared.u64 t, %1; cvt.u32.u64 %0, t; }" : "=r"(a) : "l"(p));
    return a;
}
__device__ __forceinline__ uint32_t sw128(uint32_t off) { return off ^ ((off >> 3) & 0x70); }

__device__ __forceinline__ void cpa16(uint32_t dst, const void* src) {
    asm volatile("cp.async.cg.shared.global [%0], [%1], 16;" :: "r"(dst), "l"(src));
}
#define CPC() asm volatile("cp.async.commit_group;" ::: "memory")
#define CPW(n) asm volatile("cp.async.wait_group %0;" :: "n"(n) : "memory")

__device__ __forceinline__ void ldsm4(uint32_t addr, uint32_t* r) {
    asm volatile("ldmatrix.sync.aligned.m8n8.x4.shared.b16 {%0,%1,%2,%3}, [%4];"
        : "=r"(r[0]), "=r"(r[1]), "=r"(r[2]), "=r"(r[3]) : "r"(addr));
}
__device__ __forceinline__ void ldsm4t(uint32_t addr, uint32_t* r) {
    asm volatile("ldmatrix.sync.aligned.m8n8.x4.trans.shared.b16 {%0,%1,%2,%3}, [%4];"
        : "=r"(r[0]), "=r"(r[1]), "=r"(r[2]), "=r"(r[3]) : "r"(addr));
}
// fp16 in, fp32 accumulate
__device__ __forceinline__ void mma16816(float* c, const uint32_t* a, uint32_t b0, uint32_t b1) {
    asm("mma.sync.aligned.m16n8k16.row.col.f32.f16.f16.f32 "
        "{%0,%1,%2,%3},{%4,%5,%6,%7},{%8,%9},{%0,%1,%2,%3};"
        : "+f"(c[0]), "+f"(c[1]), "+f"(c[2]), "+f"(c[3])
        : "r"(a[0]), "r"(a[1]), "r"(a[2]), "r"(a[3]), "r"(b0), "r"(b1));
}

__device__ __forceinline__ uint32_t pack_h2(float v0, float v1) {
    __half2 h = __floats2half2_rn(v0, v1);
    return *(uint32_t*)&h;
}
__device__ __forceinline__ uint32_t pack_l2(float v0, float v1) {
    __half h0 = __float2half_rn(v0), h1 = __float2half_rn(v1);
    __half2 l = __halves2half2(__float2half_rn(v0 - __half2float(h0)),
                               __float2half_rn(v1 - __half2float(h1)));
    return *(uint32_t*)&l;
}

// =====================================================================
// split kernels
// W=0: x -> hi only.  W=1: qkv_w -> hi/lo.  W=2: out_w -> hi/lo.
// =====================================================================
template<int W>
__global__ void split_kernel(const float* __restrict__ src, int n4)
{
    int i = blockIdx.x * blockDim.x + threadIdx.x;
    if (i >= n4) return;
    float4 a = *(const float4*)&src[(size_t)i * 4];
    uint2 hv = {pack_h2(a.x, a.y), pack_h2(a.z, a.w)};
    if (W == 0) {
        *(uint2*)&g_x_hi[(size_t)i * 4] = hv;
    } else {
        __half* hi = (W == 1) ? g_w_hi : g_ow_hi;
        __half* lo = (W == 1) ? g_w_lo : g_ow_lo;
        uint2 lv = {pack_l2(a.x, a.y), pack_l2(a.z, a.w)};
        *(uint2*)&hi[(size_t)i * 4] = hv;
        *(uint2*)&lo[(size_t)i * 4] = lv;
    }
}

// =====================================================================
// mma.sync GEMM (NT), fp16 2-term (A rounded, B split), fp32 acc:
// C[m,n] = sum_k A[m,k]*Bw[n,k] + bias[n]
// BM=128, BN=256, BK=64. 256 threads, 8 warps (2x4), warp tile 64x64.
// smem stage: Ah(16K)+Bh(32K)+Bl(32K)=80KB, double buffered.  (r9 config)
// MODE 0: epilogue -> q(hi) k(hi/lo) v(hi) scatter [B,H,N,D], q scaled;
// MODE 1: fp32 C.
// =====================================================================
#define GA_TILE 16384                // A: 128 rows * 128B
#define GB_TILE 32768                // B: 256 rows * 128B
#define GT_STAGE (GA_TILE + 2 * GB_TILE)       // 80KB

extern __shared__ __align__(16) char dyn_smem[];

template<int MODE>
__global__ __launch_bounds__(256, 1)
void gemm_mma(const float* __restrict__ bias, float* __restrict__ C, int K, int Nout)
{
    const __half* Ah = (MODE == 0) ? g_x_hi : g_at_hi;
    const __half* Bh = (MODE == 0) ? g_w_hi : g_ow_hi;
    const __half* Bl = (MODE == 0) ? g_w_lo : g_ow_lo;

    char* sm = (char*)(((uintptr_t)dyn_smem + 1023) & ~(uintptr_t)1023);
    uint32_t sb = smem_u32(sm);

    int tid = threadIdx.x;
    int lane = tid & 31;
    int wid = tid >> 5;              // 0..7
    int wm = wid >> 2;               // 0..1 -> rows wm*64
    int wn = wid & 3;                // 0..3 -> cols wn*64
    int m0 = blockIdx.y * 128;
    int n0 = blockIdx.x * 256;

    float acc[4][8][4];
#pragma unroll
    for (int a = 0; a < 4; a++)
#pragma unroll
        for (int b = 0; b < 8; b++)
#pragma unroll
            for (int c = 0; c < 4; c++) acc[a][b][c] = 0.f;

    // issue quarter q (0..3) of the loads for stage s (5 cpa16/thread)
    auto load_quarter = [&](int s, int k0, int q) {
        uint32_t st = sb + s * GT_STAGE;
        {
            int idx = tid + q * 256;            // A: 1 of 4 chunks
            int row = idx >> 3, seg = idx & 7;
            uint32_t off = sw128((uint32_t)(row * 128 + seg * 16));
            size_t go = (size_t)(m0 + row) * K + k0 + seg * 8;
            cpa16(st + off, Ah + go);
        }
#pragma unroll
        for (int l2 = 0; l2 < 2; l2++) {        // B: 2 of 8 chunks (hi+lo)
            int idx = tid + (q * 2 + l2) * 256;
            int row = idx >> 3, seg = idx & 7;
            uint32_t off = sw128((uint32_t)(row * 128 + seg * 16));
            size_t go = (size_t)(n0 + row) * K + k0 + seg * 8;
            cpa16(st + GA_TILE + off, Bh + go);
            cpa16(st + GA_TILE + GB_TILE + off, Bl + go);
        }
    };

    const int NIT = K / 64;
#pragma unroll
    for (int q = 0; q < 4; q++) load_quarter(0, 0, q);
    CPC();

    for (int it = 0; it < NIT; it++) {
        int s = it & 1;
        CPW(0);
        __syncthreads();

        uint32_t aH = sb + s * GT_STAGE;
        uint32_t bHs = aH + GA_TILE;
        uint32_t bLs = bHs + GB_TILE;
        bool pre = (it + 1 < NIT);

#pragma unroll
        for (int ks = 0; ks < 4; ks++) {
            if (pre) load_quarter(s ^ 1, (it + 1) * 64, ks);

            int koff = (ks * 16 + (lane >> 4) * 8) * 2;
            uint32_t ah[4][4];
#pragma unroll
            for (int tm = 0; tm < 4; tm++) {
                int ar = wm * 64 + tm * 16 + (lane & 15);
                uint32_t off = sw128((uint32_t)(ar * 128 + koff));
                ldsm4(aH + off, ah[tm]);
            }
#pragma unroll
            for (int u = 0; u < 4; u++) {
                int br = wn * 64 + u * 16 + (lane & 15);
                uint32_t off = sw128((uint32_t)(br * 128 + koff));
                uint32_t bh[4], bl[4];
                ldsm4(bHs + off, bh);
                ldsm4(bLs + off, bl);
#pragma unroll
                for (int tm = 0; tm < 4; tm++) {
                    mma16816(acc[tm][2*u],   ah[tm], bh[0], bh[2]);
                    mma16816(acc[tm][2*u+1], ah[tm], bh[1], bh[3]);
                }
#pragma unroll
                for (int tm = 0; tm < 4; tm++) {
                    mma16816(acc[tm][2*u],   ah[tm], bl[0], bl[2]);
                    mma16816(acc[tm][2*u+1], ah[tm], bl[1], bl[3]);
                }
            }
        }
        if (pre) CPC();
    }

    // ---- epilogue ----
#pragma unroll
    for (int tm = 0; tm < 4; tm++) {
#pragma unroll
        for (int j = 0; j < 8; j++) {
            int nb = n0 + wn * 64 + j * 8 + (lane & 3) * 2;
            float2 bv = *(const float2*)&bias[nb];
#pragma unroll
            for (int half = 0; half < 2; half++) {
                int m = m0 + wm * 64 + tm * 16 + (lane >> 2) + half * 8;
                float v0 = acc[tm][j][half * 2 + 0] + bv.x;
                float v1 = acc[tm][j][half * 2 + 1] + bv.y;
                if (MODE == 0) {
                    int bb = m >> 11, nn = m & (N_ - 1);
                    int which = nb >> 10, e = nb & 1023;
                    int h = e >> 6, d = e & 63;
                    size_t idx = (((size_t)bb * H_ + h) * N_ + nn) * D_ + d;
                    if (which == 0) {
                        // q: scaled (exact 2^-3), rounded only
                        *(uint32_t*)&g_qh[idx] = pack_h2(v0 * SCALE_, v1 * SCALE_);
                    } else if (which == 1) {
                        // k: hi + residual (S 2-term)
                        *(uint32_t*)&g_kh[idx] = pack_h2(v0, v1);
                        *(uint32_t*)&g_kl[idx] = pack_l2(v0, v1);
                    } else {
                        // v: rounded only (PV 1-term)
                        *(uint32_t*)&g_vh[idx] = pack_h2(v0, v1);
                    }
                } else {
                    float2 v = {v0, v1};
                    *(float2*)&C[(size_t)m * Nout + nb] = v;
                }
            }
        }
    }
}

// =====================================================================
// Flash attention, fp16:
//   S  = qh*kh + qh*kl   (2-term, fp32 acc)
//   O += Ph*Vh           (1-term, fp32 acc)
// Block = 128 threads (4 warps), q-tile 64 rows, D=64.
// smem: Ph/Qh(8K) + 2 stages x (Kh,Kl,Vh) (48KB). Double-buffered KV.
// Heavy q-tiles launch first (reversed blockIdx).
// =====================================================================
#define AKV_STAGE 24576
#define ATT_SMEM (1024 + 8192 + 2 * AKV_STAGE)

__global__ __launch_bounds__(128, 2)
void attention_kernel()
{
    char* sm = (char*)(((uintptr_t)dyn_smem + 1023) & ~(uintptr_t)1023);
    uint32_t sb = smem_u32(sm);
    const uint32_t Pha = sb;           // P hi (mainloop) / Q hi (prologue)
    const uint32_t KVb = sb + 8192;    // stage s: Kh, Kl, Vh (8KB each)

    int tid = threadIdx.x;
    int lane = tid & 31;
    int wid = tid >> 5;
    int qt = gridDim.x - 1 - blockIdx.x;   // heavy tiles first
    int bh = blockIdx.y;
    size_t base = (size_t)bh * N_ * D_;

    // prologue: Q tile (hi) + first K/V stage
#pragma unroll
    for (int l = 0; l < 4; l++) {
        int idx = tid + l * 128;
        int row = idx >> 3, seg = idx & 7;
        size_t go = base + (size_t)(qt * 64 + row) * D_ + seg * 8;
        uint32_t off = sw128((uint32_t)(row * 128 + seg * 16));
        cpa16(Pha + off, g_qh + go);
    }
    CPC();

    auto load_kv = [&](int s, int kt) {
        uint32_t kvb = KVb + s * AKV_STAGE;
#pragma unroll
        for (int l = 0; l < 4; l++) {
            int idx = tid + l * 128;
            int row = idx >> 3, seg = idx & 7;
            size_t go = base + (size_t)(kt * 64 + row) * D_ + seg * 8;
            uint32_t off = sw128((uint32_t)(row * 128 + seg * 16));
            cpa16(kvb + off, g_kh + go);
            cpa16(kvb + 8192 + off, g_kl + go);
            cpa16(kvb + 16384 + off, g_vh + go);
        }
        CPC();
    };
    load_kv(0, 0);

    CPW(0);
    __syncthreads();

    // Q fragments (pre-scaled by SCALE_)
    uint32_t qh[4][4];
    int ar = wid * 16 + (lane & 15);
#pragma unroll
    for (int ks = 0; ks < 4; ks++) {
        uint32_t off = sw128((uint32_t)(ar * 128 + (ks * 16 + (lane >> 4) * 8) * 2));
        ldsm4(Pha + off, qh[ks]);
    }

    float o[8][4];
#pragma unroll
    for (int j = 0; j < 8; j++)
#pragma unroll
        for (int e = 0; e < 4; e++) o[j][e] = 0.f;
    float m0r = -1e30f, m1r = -1e30f, l0 = 0.f, l1 = 0.f;

    int rowl0 = wid * 16 + (lane >> 2);
    int rowl1 = rowl0 + 8;

    for (int kt = 0; kt <= qt; kt++) {
        int s = kt & 1;
        __syncthreads();
        if (kt < qt) load_kv(s ^ 1, kt + 1);
        if (kt < qt) { CPW(1); } else { CPW(0); }
        __syncthreads();

        uint32_t Kh = KVb + s * AKV_STAGE;
        uint32_t Kl = Kh + 8192;
        uint32_t Vh = Kh + 16384;

        // ---- S = Q K^T (2-term fp16, fp32 acc) ----
        float sc[8][4];
#pragma unroll
        for (int j = 0; j < 8; j++)
#pragma unroll
            for (int e = 0; e < 4; e++) sc[j][e] = 0.f;

#pragma unroll
        for (int ks = 0; ks < 4; ks++) {
            int koff = (ks * 16 + (lane >> 4) * 8) * 2;
            uint32_t kh4[4][4], kl4[4][4];
#pragma unroll
            for (int u = 0; u < 4; u++) {
                int br = u * 16 + (lane & 15);
                uint32_t off = sw128((uint32_t)(br * 128 + koff));
                ldsm4(Kh + off, kh4[u]);
                ldsm4(Kl + off, kl4[u]);
            }
#pragma unroll
            for (int u = 0; u < 4; u++) {
                mma16816(sc[2*u],   qh[ks], kh4[u][0], kh4[u][2]);
                mma16816(sc[2*u+1], qh[ks], kh4[u][1], kh4[u][3]);
            }
#pragma unroll
            for (int u = 0; u < 4; u++) {
                mma16816(sc[2*u],   qh[ks], kl4[u][0], kl4[u][2]);
                mma16816(sc[2*u+1], qh[ks], kl4[u][1], kl4[u][3]);
            }
        }

        if (kt == qt) {
#pragma unroll
            for (int j = 0; j < 8; j++) {
                int c = j * 8 + (lane & 3) * 2;
                if (c     > rowl0) sc[j][0] = -1e30f;
                if (c + 1 > rowl0) sc[j][1] = -1e30f;
                if (c     > rowl1) sc[j][2] = -1e30f;
                if (c + 1 > rowl1) sc[j][3] = -1e30f;
            }
        }

        // ---- online softmax ----
        float t0 = -1e30f, t1 = -1e30f;
#pragma unroll
        for (int j = 0; j < 8; j++) {
            t0 = fmaxf(t0, fmaxf(sc[j][0], sc[j][1]));
            t1 = fmaxf(t1, fmaxf(sc[j][2], sc[j][3]));
        }
        t0 = fmaxf(t0, __shfl_xor_sync(0xffffffff, t0, 1));
        t0 = fmaxf(t0, __shfl_xor_sync(0xffffffff, t0, 2));
        t1 = fmaxf(t1, __shfl_xor_sync(0xffffffff, t1, 1));
        t1 = fmaxf(t1, __shfl_xor_sync(0xffffffff, t1, 2));
        float nm0 = fmaxf(m0r, t0), nm1 = fmaxf(m1r, t1);
        float f0 = __expf(m0r - nm0), f1 = __expf(m1r - nm1);
        m0r = nm0; m1r = nm1;

        float s0 = 0.f, s1 = 0.f;
#pragma unroll
        for (int j = 0; j < 8; j++) {
            float p0 = __expf(sc[j][0] - nm0);
            float p1 = __expf(sc[j][1] - nm0);
            float p2 = __expf(sc[j][2] - nm1);
            float p3 = __expf(sc[j][3] - nm1);
            s0 += p0 + p1; s1 += p2 + p3;
            uint32_t coff = (uint32_t)(j * 16 + (lane & 3) * 4);
            uint32_t off0 = sw128((uint32_t)(rowl0 * 128) + coff);
            uint32_t off1 = sw128((uint32_t)(rowl1 * 128) + coff);
            *(uint32_t*)(sm + off0) = pack_h2(p0, p1);
            *(uint32_t*)(sm + off1) = pack_h2(p2, p3);
            o[j][0] *= f0; o[j][1] *= f0; o[j][2] *= f1; o[j][3] *= f1;
        }
        s0 += __shfl_xor_sync(0xffffffff, s0, 1);
        s0 += __shfl_xor_sync(0xffffffff, s0, 2);
        s1 += __shfl_xor_sync(0xffffffff, s1, 1);
        s1 += __shfl_xor_sync(0xffffffff, s1, 2);
        l0 = l0 * f0 + s0;
        l1 = l1 * f1 + s1;
        __syncwarp();      // P writes (warp-local rows) visible before ldsm

        // ---- O += P V (1-term) ----
#pragma unroll
        for (int ks = 0; ks < 4; ks++) {
            uint32_t offp = sw128((uint32_t)(ar * 128 + (ks * 16 + (lane >> 4) * 8) * 2));
            uint32_t ph4[4];
            ldsm4(Pha + offp, ph4);
            uint32_t vh4[4][4];
#pragma unroll
            for (int u = 0; u < 4; u++) {
                int vr = ks * 16 + ((lane >> 4) << 3) + (lane & 7);
                int vc = u * 16 + ((lane >> 3) & 1) * 8;
                uint32_t offv = sw128((uint32_t)(vr * 128 + vc * 2));
                ldsm4t(Vh + offv, vh4[u]);
            }
#pragma unroll
            for (int u = 0; u < 4; u++) {
                mma16816(o[2*u],   ph4, vh4[u][0], vh4[u][2]);
                mma16816(o[2*u+1], ph4, vh4[u][1], vh4[u][3]);
            }
        }
    }

    // ---- epilogue: normalize + write fp16 hi [B,N,E] ----
    float inv0 = 1.f / l0, inv1 = 1.f / l1;
    int b = bh >> 4, h = bh & 15;
    int n0g = qt * 64 + rowl0;
#pragma unroll
    for (int j = 0; j < 8; j++) {
        int d = h * 64 + j * 8 + (lane & 3) * 2;
        size_t i0 = ((size_t)b * N_ + n0g) * E_ + d;
        size_t i1 = ((size_t)b * N_ + n0g + 8) * E_ + d;
        *(uint32_t*)&g_at_hi[i0] = pack_h2(o[j][0] * inv0, o[j][1] * inv0);
        *(uint32_t*)&g_at_hi[i1] = pack_h2(o[j][2] * inv1, o[j][3] * inv1);
    }
}

// =====================================================================
// launch
// =====================================================================
extern "C" void kernel_launch(void* const* d_in, const int* in_sizes, int n_in,
                              void* d_out, int out_size)
{
    const float* x     = (const float*)d_in[0];
    const float* qkv_w = (const float*)d_in[1];
    const float* qkv_b = (const float*)d_in[2];
    const float* out_w = (const float*)d_in[3];
    const float* out_b = (const float*)d_in[4];
    float* out = (float*)d_out;

    const int M = B_ * N_;
    const int gemm_smem = 2 * GT_STAGE + 1024;   // 161 KB

    cudaFuncSetAttribute(gemm_mma<0>, cudaFuncAttributeMaxDynamicSharedMemorySize, gemm_smem);
    cudaFuncSetAttribute(gemm_mma<1>, cudaFuncAttributeMaxDynamicSharedMemorySize, gemm_smem);
    cudaFuncSetAttribute(attention_kernel, cudaFuncAttributeMaxDynamicSharedMemorySize, ATT_SMEM);

    split_kernel<0><<<(M * E_ / 4 + 255) / 256, 256>>>(x, M * E_ / 4);
    split_kernel<1><<<(3 * E_ * E_ / 4 + 255) / 256, 256>>>(qkv_w, 3 * E_ * E_ / 4);
    split_kernel<2><<<(E_ * E_ / 4 + 255) / 256, 256>>>(out_w, E_ * E_ / 4);

    gemm_mma<0><<<dim3(3 * E_ / 256, M / 128), 256, gemm_smem>>>(qkv_b, nullptr, E_, 3 * E_);

    attention_kernel<<<dim3(N_ / 64, B_ * H_), 128, ATT_SMEM>>>();

    gemm_mma<1><<<dim3(E_ / 256, M / 128), 256, gemm_smem>>>(out_b, out, E_, E_);
}

// round 12
// speedup vs baseline: 1.4467x; 1.2338x over previous
#include <cuda_runtime.h>
#include <cuda_fp16.h>
#include <cstdint>

// ---------------- problem constants ----------------
#define B_   2
#define N_   2048
#define E_   1024
#define H_   16
#define D_   64
#define SCALE_ 0.125f   // 64^-0.5

// ---------------- device scratch (no allocs allowed) ----------------
__device__ __half g_x_hi[(size_t)B_*N_*E_];            // x rounded
__device__ __half g_w_hi[(size_t)3*E_*E_];             // w rounded (QKV 1-term)
__device__ __half g_ow_hi[(size_t)E_*E_];
__device__ __half g_ow_lo[(size_t)E_*E_];              // residual (out-proj 2-term)
__device__ __half g_qh[(size_t)B_*H_*N_*D_];           // rounded, pre-scaled by SCALE_
__device__ __half g_kh[(size_t)B_*H_*N_*D_];
__device__ __half g_kl[(size_t)B_*H_*N_*D_];           // residual (S 2-term)
__device__ __half g_vh[(size_t)B_*H_*N_*D_];           // rounded (PV 1-term)
__device__ __half g_at_hi[(size_t)B_*N_*E_];           // attention out rounded

// =====================================================================
// helpers
// =====================================================================
__device__ __forceinline__ uint32_t smem_u32(const void* p) {
    uint32_t a;
    asm("{ .reg .u64 t; cvta.to.shared.u64 t, %1; cvt.u32.u64 %0, t; }" : "=r"(a) : "l"(p));
    return a;
}
__device__ __forceinline__ uint32_t sw128(uint32_t off) { return off ^ ((off >> 3) & 0x70); }

__device__ __forceinline__ void cpa16(uint32_t dst, const void* src) {
    asm volatile("cp.async.cg.shared.global [%0], [%1], 16;" :: "r"(dst), "l"(src));
}
#define CPC() asm volatile("cp.async.commit_group;" ::: "memory")
#define CPW(n) asm volatile("cp.async.wait_group %0;" :: "n"(n) : "memory")

__device__ __forceinline__ void ldsm4(uint32_t addr, uint32_t* r) {
    asm volatile("ldmatrix.sync.aligned.m8n8.x4.shared.b16 {%0,%1,%2,%3}, [%4];"
        : "=r"(r[0]), "=r"(r[1]), "=r"(r[2]), "=r"(r[3]) : "r"(addr));
}
__device__ __forceinline__ void ldsm4t(uint32_t addr, uint32_t* r) {
    asm volatile("ldmatrix.sync.aligned.m8n8.x4.trans.shared.b16 {%0,%1,%2,%3}, [%4];"
        : "=r"(r[0]), "=r"(r[1]), "=r"(r[2]), "=r"(r[3]) : "r"(addr));
}
// fp16 in, fp32 accumulate
__device__ __forceinline__ void mma16816(float* c, const uint32_t* a, uint32_t b0, uint32_t b1) {
    asm("mma.sync.aligned.m16n8k16.row.col.f32.f16.f16.f32 "
        "{%0,%1,%2,%3},{%4,%5,%6,%7},{%8,%9},{%0,%1,%2,%3};"
        : "+f"(c[0]), "+f"(c[1]), "+f"(c[2]), "+f"(c[3])
        : "r"(a[0]), "r"(a[1]), "r"(a[2]), "r"(a[3]), "r"(b0), "r"(b1));
}

__device__ __forceinline__ uint32_t pack_h2(float v0, float v1) {
    __half2 h = __floats2half2_rn(v0, v1);
    return *(uint32_t*)&h;
}
__device__ __forceinline__ uint32_t pack_l2(float v0, float v1) {
    __half h0 = __float2half_rn(v0), h1 = __float2half_rn(v1);
    __half2 l = __halves2half2(__float2half_rn(v0 - __half2float(h0)),
                               __float2half_rn(v1 - __half2float(h1)));
    return *(uint32_t*)&l;
}

// =====================================================================
// split kernels
// W=0: x -> hi.  W=1: qkv_w -> hi only.  W=2: out_w -> hi/lo.
// =====================================================================
template<int W>
__global__ void split_kernel(const float* __restrict__ src, int n4)
{
    int i = blockIdx.x * blockDim.x + threadIdx.x;
    if (i >= n4) return;
    float4 a = *(const float4*)&src[(size_t)i * 4];
    uint2 hv = {pack_h2(a.x, a.y), pack_h2(a.z, a.w)};
    if (W == 0) {
        *(uint2*)&g_x_hi[(size_t)i * 4] = hv;
    } else if (W == 1) {
        *(uint2*)&g_w_hi[(size_t)i * 4] = hv;
    } else {
        uint2 lv = {pack_l2(a.x, a.y), pack_l2(a.z, a.w)};
        *(uint2*)&g_ow_hi[(size_t)i * 4] = hv;
        *(uint2*)&g_ow_lo[(size_t)i * 4] = lv;
    }
}

// =====================================================================
// mma.sync GEMM (NT), fp16, fp32 acc. TB = # B terms (1 or 2).
// C[m,n] = sum_k A[m,k]*Bw[n,k] + bias[n]
// BM=128, BN=256, BK=64. 256 threads, 8 warps (2x4), warp tile 64x64.
// MODE 0 (TB=1): epilogue -> q(hi) k(hi/lo) v(hi) scatter, q scaled.
// MODE 1 (TB=2): fp32 C row-major.
// =====================================================================
#define GA_TILE 16384                // A: 128 rows * 128B
#define GB_TILE 32768                // B: 256 rows * 128B

extern __shared__ __align__(16) char dyn_smem[];

template<int MODE, int TB>
__global__ __launch_bounds__(256, 1)
void gemm_mma(const float* __restrict__ bias, float* __restrict__ C, int K, int Nout)
{
    constexpr int STAGE = GA_TILE + TB * GB_TILE;
    const __half* Ah = (MODE == 0) ? g_x_hi : g_at_hi;
    const __half* Bh = (MODE == 0) ? g_w_hi : g_ow_hi;
    const __half* Bl = g_ow_lo;     // used only when TB==2

    char* sm = (char*)(((uintptr_t)dyn_smem + 1023) & ~(uintptr_t)1023);
    uint32_t sb = smem_u32(sm);

    int tid = threadIdx.x;
    int lane = tid & 31;
    int wid = tid >> 5;              // 0..7
    int wm = wid >> 2;               // 0..1 -> rows wm*64
    int wn = wid & 3;                // 0..3 -> cols wn*64
    int m0 = blockIdx.y * 128;
    int n0 = blockIdx.x * 256;

    float acc[4][8][4];
#pragma unroll
    for (int a = 0; a < 4; a++)
#pragma unroll
        for (int b = 0; b < 8; b++)
#pragma unroll
            for (int c = 0; c < 4; c++) acc[a][b][c] = 0.f;

    // issue quarter q (0..3) of stage loads
    auto load_quarter = [&](int s, int k0, int q) {
        uint32_t st = sb + s * STAGE;
        {
            int idx = tid + q * 256;            // A: 1 of 4 chunks
            int row = idx >> 3, seg = idx & 7;
            uint32_t off = sw128((uint32_t)(row * 128 + seg * 16));
            size_t go = (size_t)(m0 + row) * K + k0 + seg * 8;
            cpa16(st + off, Ah + go);
        }
#pragma unroll
        for (int l2 = 0; l2 < 2; l2++) {        // B: 2 of 8 chunks
            int idx = tid + (q * 2 + l2) * 256;
            int row = idx >> 3, seg = idx & 7;
            uint32_t off = sw128((uint32_t)(row * 128 + seg * 16));
            size_t go = (size_t)(n0 + row) * K + k0 + seg * 8;
            cpa16(st + GA_TILE + off, Bh + go);
            if (TB == 2) cpa16(st + GA_TILE + GB_TILE + off, Bl + go);
        }
    };

    const int NIT = K / 64;
#pragma unroll
    for (int q = 0; q < 4; q++) load_quarter(0, 0, q);
    CPC();

    for (int it = 0; it < NIT; it++) {
        int s = it & 1;
        CPW(0);
        __syncthreads();

        uint32_t aH = sb + s * STAGE;
        uint32_t bHs = aH + GA_TILE;
        uint32_t bLs = bHs + GB_TILE;
        bool pre = (it + 1 < NIT);

#pragma unroll
        for (int ks = 0; ks < 4; ks++) {
            if (pre) load_quarter(s ^ 1, (it + 1) * 64, ks);

            int koff = (ks * 16 + (lane >> 4) * 8) * 2;
            uint32_t ah[4][4];
#pragma unroll
            for (int tm = 0; tm < 4; tm++) {
                int ar = wm * 64 + tm * 16 + (lane & 15);
                uint32_t off = sw128((uint32_t)(ar * 128 + koff));
                ldsm4(aH + off, ah[tm]);
            }
#pragma unroll
            for (int u = 0; u < 4; u++) {
                int br = wn * 64 + u * 16 + (lane & 15);
                uint32_t off = sw128((uint32_t)(br * 128 + koff));
                uint32_t bh[4];
                ldsm4(bHs + off, bh);
#pragma unroll
                for (int tm = 0; tm < 4; tm++) {
                    mma16816(acc[tm][2*u],   ah[tm], bh[0], bh[2]);
                    mma16816(acc[tm][2*u+1], ah[tm], bh[1], bh[3]);
                }
                if (TB == 2) {
                    uint32_t bl[4];
                    ldsm4(bLs + off, bl);
#pragma unroll
                    for (int tm = 0; tm < 4; tm++) {
                        mma16816(acc[tm][2*u],   ah[tm], bl[0], bl[2]);
                        mma16816(acc[tm][2*u+1], ah[tm], bl[1], bl[3]);
                    }
                }
            }
        }
        if (pre) CPC();
    }

    // ---- epilogue ----
#pragma unroll
    for (int tm = 0; tm < 4; tm++) {
#pragma unroll
        for (int j = 0; j < 8; j++) {
            int nb = n0 + wn * 64 + j * 8 + (lane & 3) * 2;
            float2 bv = *(const float2*)&bias[nb];
#pragma unroll
            for (int half = 0; half < 2; half++) {
                int m = m0 + wm * 64 + tm * 16 + (lane >> 2) + half * 8;
                float v0 = acc[tm][j][half * 2 + 0] + bv.x;
                float v1 = acc[tm][j][half * 2 + 1] + bv.y;
                if (MODE == 0) {
                    int bb = m >> 11, nn = m & (N_ - 1);
                    int which = nb >> 10, e = nb & 1023;
                    int h = e >> 6, d = e & 63;
                    size_t idx = (((size_t)bb * H_ + h) * N_ + nn) * D_ + d;
                    if (which == 0) {
                        *(uint32_t*)&g_qh[idx] = pack_h2(v0 * SCALE_, v1 * SCALE_);
                    } else if (which == 1) {
                        *(uint32_t*)&g_kh[idx] = pack_h2(v0, v1);
                        *(uint32_t*)&g_kl[idx] = pack_l2(v0, v1);
                    } else {
                        *(uint32_t*)&g_vh[idx] = pack_h2(v0, v1);
                    }
                } else {
                    float2 v = {v0, v1};
                    *(float2*)&C[(size_t)m * Nout + nb] = v;
                }
            }
        }
    }
}

// =====================================================================
// Flash attention, fp16 (unchanged from r11):
//   S  = qh*kh + qh*kl   (2-term, fp32 acc)
//   O += Ph*Vh           (1-term, fp32 acc)
// Block = 128 threads (4 warps), q-tile 64 rows, D=64.
// =====================================================================
#define AKV_STAGE 24576
#define ATT_SMEM (1024 + 8192 + 2 * AKV_STAGE)

__global__ __launch_bounds__(128, 2)
void attention_kernel()
{
    char* sm = (char*)(((uintptr_t)dyn_smem + 1023) & ~(uintptr_t)1023);
    uint32_t sb = smem_u32(sm);
    const uint32_t Pha = sb;           // P hi (mainloop) / Q hi (prologue)
    const uint32_t KVb = sb + 8192;    // stage s: Kh, Kl, Vh (8KB each)

    int tid = threadIdx.x;
    int lane = tid & 31;
    int wid = tid >> 5;
    int qt = gridDim.x - 1 - blockIdx.x;   // heavy tiles first
    int bh = blockIdx.y;
    size_t base = (size_t)bh * N_ * D_;

#pragma unroll
    for (int l = 0; l < 4; l++) {
        int idx = tid + l * 128;
        int row = idx >> 3, seg = idx & 7;
        size_t go = base + (size_t)(qt * 64 + row) * D_ + seg * 8;
        uint32_t off = sw128((uint32_t)(row * 128 + seg * 16));
        cpa16(Pha + off, g_qh + go);
    }
    CPC();

    auto load_kv = [&](int s, int kt) {
        uint32_t kvb = KVb + s * AKV_STAGE;
#pragma unroll
        for (int l = 0; l < 4; l++) {
            int idx = tid + l * 128;
            int row = idx >> 3, seg = idx & 7;
            size_t go = base + (size_t)(kt * 64 + row) * D_ + seg * 8;
            uint32_t off = sw128((uint32_t)(row * 128 + seg * 16));
            cpa16(kvb + off, g_kh + go);
            cpa16(kvb + 8192 + off, g_kl + go);
            cpa16(kvb + 16384 + off, g_vh + go);
        }
        CPC();
    };
    load_kv(0, 0);

    CPW(0);
    __syncthreads();

    uint32_t qh[4][4];
    int ar = wid * 16 + (lane & 15);
#pragma unroll
    for (int ks = 0; ks < 4; ks++) {
        uint32_t off = sw128((uint32_t)(ar * 128 + (ks * 16 + (lane >> 4) * 8) * 2));
        ldsm4(Pha + off, qh[ks]);
    }

    float o[8][4];
#pragma unroll
    for (int j = 0; j < 8; j++)
#pragma unroll
        for (int e = 0; e < 4; e++) o[j][e] = 0.f;
    float m0r = -1e30f, m1r = -1e30f, l0 = 0.f, l1 = 0.f;

    int rowl0 = wid * 16 + (lane >> 2);
    int rowl1 = rowl0 + 8;

    for (int kt = 0; kt <= qt; kt++) {
        int s = kt & 1;
        __syncthreads();
        if (kt < qt) load_kv(s ^ 1, kt + 1);
        if (kt < qt) { CPW(1); } else { CPW(0); }
        __syncthreads();

        uint32_t Kh = KVb + s * AKV_STAGE;
        uint32_t Kl = Kh + 8192;
        uint32_t Vh = Kh + 16384;

        float sc[8][4];
#pragma unroll
        for (int j = 0; j < 8; j++)
#pragma unroll
            for (int e = 0; e < 4; e++) sc[j][e] = 0.f;

#pragma unroll
        for (int ks = 0; ks < 4; ks++) {
            int koff = (ks * 16 + (lane >> 4) * 8) * 2;
            uint32_t kh4[4][4], kl4[4][4];
#pragma unroll
            for (int u = 0; u < 4; u++) {
                int br = u * 16 + (lane & 15);
                uint32_t off = sw128((uint32_t)(br * 128 + koff));
                ldsm4(Kh + off, kh4[u]);
                ldsm4(Kl + off, kl4[u]);
            }
#pragma unroll
            for (int u = 0; u < 4; u++) {
                mma16816(sc[2*u],   qh[ks], kh4[u][0], kh4[u][2]);
                mma16816(sc[2*u+1], qh[ks], kh4[u][1], kh4[u][3]);
            }
#pragma unroll
            for (int u = 0; u < 4; u++) {
                mma16816(sc[2*u],   qh[ks], kl4[u][0], kl4[u][2]);
                mma16816(sc[2*u+1], qh[ks], kl4[u][1], kl4[u][3]);
            }
        }

        if (kt == qt) {
#pragma unroll
            for (int j = 0; j < 8; j++) {
                int c = j * 8 + (lane & 3) * 2;
                if (c     > rowl0) sc[j][0] = -1e30f;
                if (c + 1 > rowl0) sc[j][1] = -1e30f;
                if (c     > rowl1) sc[j][2] = -1e30f;
                if (c + 1 > rowl1) sc[j][3] = -1e30f;
            }
        }

        float t0 = -1e30f, t1 = -1e30f;
#pragma unroll
        for (int j = 0; j < 8; j++) {
            t0 = fmaxf(t0, fmaxf(sc[j][0], sc[j][1]));
            t1 = fmaxf(t1, fmaxf(sc[j][2], sc[j][3]));
        }
        t0 = fmaxf(t0, __shfl_xor_sync(0xffffffff, t0, 1));
        t0 = fmaxf(t0, __shfl_xor_sync(0xffffffff, t0, 2));
        t1 = fmaxf(t1, __shfl_xor_sync(0xffffffff, t1, 1));
        t1 = fmaxf(t1, __shfl_xor_sync(0xffffffff, t1, 2));
        float nm0 = fmaxf(m0r, t0), nm1 = fmaxf(m1r, t1);
        float f0 = __expf(m0r - nm0), f1 = __expf(m1r - nm1);
        m0r = nm0; m1r = nm1;

        float s0 = 0.f, s1 = 0.f;
#pragma unroll
        for (int j = 0; j < 8; j++) {
            float p0 = __expf(sc[j][0] - nm0);
            float p1 = __expf(sc[j][1] - nm0);
            float p2 = __expf(sc[j][2] - nm1);
            float p3 = __expf(sc[j][3] - nm1);
            s0 += p0 + p1; s1 += p2 + p3;
            uint32_t coff = (uint32_t)(j * 16 + (lane & 3) * 4);
            uint32_t off0 = sw128((uint32_t)(rowl0 * 128) + coff);
            uint32_t off1 = sw128((uint32_t)(rowl1 * 128) + coff);
            *(uint32_t*)(sm + off0) = pack_h2(p0, p1);
            *(uint32_t*)(sm + off1) = pack_h2(p2, p3);
            o[j][0] *= f0; o[j][1] *= f0; o[j][2] *= f1; o[j][3] *= f1;
        }
        s0 += __shfl_xor_sync(0xffffffff, s0, 1);
        s0 += __shfl_xor_sync(0xffffffff, s0, 2);
        s1 += __shfl_xor_sync(0xffffffff, s1, 1);
        s1 += __shfl_xor_sync(0xffffffff, s1, 2);
        l0 = l0 * f0 + s0;
        l1 = l1 * f1 + s1;
        __syncwarp();

#pragma unroll
        for (int ks = 0; ks < 4; ks++) {
            uint32_t offp = sw128((uint32_t)(ar * 128 + (ks * 16 + (lane >> 4) * 8) * 2));
            uint32_t ph4[4];
            ldsm4(Pha + offp, ph4);
            uint32_t vh4[4][4];
#pragma unroll
            for (int u = 0; u < 4; u++) {
                int vr = ks * 16 + ((lane >> 4) << 3) + (lane & 7);
                int vc = u * 16 + ((lane >> 3) & 1) * 8;
                uint32_t offv = sw128((uint32_t)(vr * 128 + vc * 2));
                ldsm4t(Vh + offv, vh4[u]);
            }
#pragma unroll
            for (int u = 0; u < 4; u++) {
                mma16816(o[2*u],   ph4, vh4[u][0], vh4[u][2]);
                mma16816(o[2*u+1], ph4, vh4[u][1], vh4[u][3]);
            }
        }
    }

    float inv0 = 1.f / l0, inv1 = 1.f / l1;
    int b = bh >> 4, h = bh & 15;
    int n0g = qt * 64 + rowl0;
#pragma unroll
    for (int j = 0; j < 8; j++) {
        int d = h * 64 + j * 8 + (lane & 3) * 2;
        size_t i0 = ((size_t)b * N_ + n0g) * E_ + d;
        size_t i1 = ((size_t)b * N_ + n0g + 8) * E_ + d;
        *(uint32_t*)&g_at_hi[i0] = pack_h2(o[j][0] * inv0, o[j][1] * inv0);
        *(uint32_t*)&g_at_hi[i1] = pack_h2(o[j][2] * inv1, o[j][3] * inv1);
    }
}

// =====================================================================
// launch
// =====================================================================
extern "C" void kernel_launch(void* const* d_in, const int* in_sizes, int n_in,
                              void* d_out, int out_size)
{
    const float* x     = (const float*)d_in[0];
    const float* qkv_w = (const float*)d_in[1];
    const float* qkv_b = (const float*)d_in[2];
    const float* out_w = (const float*)d_in[3];
    const float* out_b = (const float*)d_in[4];
    float* out = (float*)d_out;

    const int M = B_ * N_;
    const int qkv_smem = 2 * (GA_TILE + 1 * GB_TILE) + 1024;   // 97 KB
    const int op_smem  = 2 * (GA_TILE + 2 * GB_TILE) + 1024;   // 161 KB

    cudaFuncSetAttribute(gemm_mma<0,1>, cudaFuncAttributeMaxDynamicSharedMemorySize, qkv_smem);
    cudaFuncSetAttribute(gemm_mma<1,2>, cudaFuncAttributeMaxDynamicSharedMemorySize, op_smem);
    cudaFuncSetAttribute(attention_kernel, cudaFuncAttributeMaxDynamicSharedMemorySize, ATT_SMEM);

    split_kernel<0><<<(M * E_ / 4 + 255) / 256, 256>>>(x, M * E_ / 4);
    split_kernel<1><<<(3 * E_ * E_ / 4 + 255) / 256, 256>>>(qkv_w, 3 * E_ * E_ / 4);
    split_kernel<2><<<(E_ * E_ / 4 + 255) / 256, 256>>>(out_w, E_ * E_ / 4);

    gemm_mma<0,1><<<dim3(3 * E_ / 256, M / 128), 256, qkv_smem>>>(qkv_b, nullptr, E_, 3 * E_);

    attention_kernel<<<dim3(N_ / 64, B_ * H_), 128, ATT_SMEM>>>();

    gemm_mma<1,2><<<dim3(E_ / 256, M / 128), 256, op_smem>>>(out_b, out, E_, E_);
}

// round 14
// speedup vs baseline: 1.7933x; 1.2395x over previous
#include <cuda_runtime.h>
#include <cuda_fp16.h>
#include <cstdint>

// ---------------- problem constants ----------------
#define B_   2
#define N_   2048
#define E_   1024
#define H_   16
#define D_   64
#define SCALE_ 0.125f   // 64^-0.5

// ---------------- device scratch (no allocs allowed) ----------------
__device__ __half g_x_hi[(size_t)B_*N_*E_];            // x rounded
__device__ __half g_w_hi[(size_t)3*E_*E_];             // qkv_w rounded
__device__ __half g_ow_hi[(size_t)E_*E_];              // out_w rounded
__device__ __half g_qh[(size_t)B_*H_*N_*D_];           // rounded, pre-scaled by SCALE_
__device__ __half g_kh[(size_t)B_*H_*N_*D_];           // rounded (S 1-term)
__device__ __half g_vh[(size_t)B_*H_*N_*D_];           // rounded (PV 1-term)
__device__ __half g_at_hi[(size_t)B_*N_*E_];           // attention out rounded

// =====================================================================
// helpers
// =====================================================================
__device__ __forceinline__ uint32_t smem_u32(const void* p) {
    uint32_t a;
    asm("{ .reg .u64 t; cvta.to.shared.u64 t, %1; cvt.u32.u64 %0, t; }" : "=r"(a) : "l"(p));
    return a;
}
__device__ __forceinline__ uint32_t sw128(uint32_t off) { return off ^ ((off >> 3) & 0x70); }

__device__ __forceinline__ void cpa16(uint32_t dst, const void* src) {
    asm volatile("cp.async.cg.shared.global [%0], [%1], 16;" :: "r"(dst), "l"(src));
}
#define CPC() asm volatile("cp.async.commit_group;" ::: "memory")
#define CPW(n) asm volatile("cp.async.wait_group %0;" :: "n"(n) : "memory")

__device__ __forceinline__ void ldsm4(uint32_t addr, uint32_t* r) {
    asm volatile("ldmatrix.sync.aligned.m8n8.x4.shared.b16 {%0,%1,%2,%3}, [%4];"
        : "=r"(r[0]), "=r"(r[1]), "=r"(r[2]), "=r"(r[3]) : "r"(addr));
}
__device__ __forceinline__ void ldsm4t(uint32_t addr, uint32_t* r) {
    asm volatile("ldmatrix.sync.aligned.m8n8.x4.trans.shared.b16 {%0,%1,%2,%3}, [%4];"
        : "=r"(r[0]), "=r"(r[1]), "=r"(r[2]), "=r"(r[3]) : "r"(addr));
}
// fp16 in, fp32 accumulate
__device__ __forceinline__ void mma16816(float* c, const uint32_t* a, uint32_t b0, uint32_t b1) {
    asm("mma.sync.aligned.m16n8k16.row.col.f32.f16.f16.f32 "
        "{%0,%1,%2,%3},{%4,%5,%6,%7},{%8,%9},{%0,%1,%2,%3};"
        : "+f"(c[0]), "+f"(c[1]), "+f"(c[2]), "+f"(c[3])
        : "r"(a[0]), "r"(a[1]), "r"(a[2]), "r"(a[3]), "r"(b0), "r"(b1));
}

__device__ __forceinline__ uint32_t pack_h2(float v0, float v1) {
    __half2 h = __floats2half2_rn(v0, v1);
    return *(uint32_t*)&h;
}

// =====================================================================
// split kernel: fp32 -> fp16 (rounded). W selects destination.
// =====================================================================
template<int W>
__global__ void split_kernel(const float* __restrict__ src, int n4)
{
    __half* dst = (W == 0) ? g_x_hi : (W == 1) ? g_w_hi : g_ow_hi;
    int i = blockIdx.x * blockDim.x + threadIdx.x;
    if (i >= n4) return;
    float4 a = *(const float4*)&src[(size_t)i * 4];
    uint2 hv = {pack_h2(a.x, a.y), pack_h2(a.z, a.w)};
    *(uint2*)&dst[(size_t)i * 4] = hv;
}

// =====================================================================
// mma.sync GEMM (NT), fp16 1-term, fp32 acc:
// C[m,n] = sum_k A[m,k]*Bw[n,k] + bias[n]
// BM=128, BN=256, BK=64. 256 threads, 8 warps (2x4), warp tile 64x64.
// MODE 0: epilogue -> q/k/v (rounded) scatter [B,H,N,D], q scaled.
// MODE 1: fp32 C row-major.
// =====================================================================
#define GA_TILE 16384                // A: 128 rows * 128B
#define GB_TILE 32768                // B: 256 rows * 128B
#define GT_STAGE (GA_TILE + GB_TILE) // 48KB

extern __shared__ __align__(16) char dyn_smem[];

template<int MODE>
__global__ __launch_bounds__(256, 1)
void gemm_mma(const float* __restrict__ bias, float* __restrict__ C, int K, int Nout)
{
    const __half* Ah = (MODE == 0) ? g_x_hi : g_at_hi;
    const __half* Bh = (MODE == 0) ? g_w_hi : g_ow_hi;

    char* sm = (char*)(((uintptr_t)dyn_smem + 1023) & ~(uintptr_t)1023);
    uint32_t sb = smem_u32(sm);

    int tid = threadIdx.x;
    int lane = tid & 31;
    int wid = tid >> 5;              // 0..7
    int wm = wid >> 2;               // 0..1 -> rows wm*64
    int wn = wid & 3;                // 0..3 -> cols wn*64
    int m0 = blockIdx.y * 128;
    int n0 = blockIdx.x * 256;

    float acc[4][8][4];
#pragma unroll
    for (int a = 0; a < 4; a++)
#pragma unroll
        for (int b = 0; b < 8; b++)
#pragma unroll
            for (int c = 0; c < 4; c++) acc[a][b][c] = 0.f;

    // issue quarter q (0..3) of stage loads (3 cpa16/thread)
    auto load_quarter = [&](int s, int k0, int q) {
        uint32_t st = sb + s * GT_STAGE;
        {
            int idx = tid + q * 256;            // A: 1 of 4 chunks
            int row = idx >> 3, seg = idx & 7;
            uint32_t off = sw128((uint32_t)(row * 128 + seg * 16));
            size_t go = (size_t)(m0 + row) * K + k0 + seg * 8;
            cpa16(st + off, Ah + go);
        }
#pragma unroll
        for (int l2 = 0; l2 < 2; l2++) {        // B: 2 of 8 chunks
            int idx = tid + (q * 2 + l2) * 256;
            int row = idx >> 3, seg = idx & 7;
            uint32_t off = sw128((uint32_t)(row * 128 + seg * 16));
            size_t go = (size_t)(n0 + row) * K + k0 + seg * 8;
            cpa16(st + GA_TILE + off, Bh + go);
        }
    };

    const int NIT = K / 64;
#pragma unroll
    for (int q = 0; q < 4; q++) load_quarter(0, 0, q);
    CPC();

    for (int it = 0; it < NIT; it++) {
        int s = it & 1;
        CPW(0);
        __syncthreads();

        uint32_t aH = sb + s * GT_STAGE;
        uint32_t bHs = aH + GA_TILE;
        bool pre = (it + 1 < NIT);

#pragma unroll
        for (int ks = 0; ks < 4; ks++) {
            if (pre) load_quarter(s ^ 1, (it + 1) * 64, ks);

            int koff = (ks * 16 + (lane >> 4) * 8) * 2;
            uint32_t ah[4][4];
#pragma unroll
            for (int tm = 0; tm < 4; tm++) {
                int ar = wm * 64 + tm * 16 + (lane & 15);
                uint32_t off = sw128((uint32_t)(ar * 128 + koff));
                ldsm4(aH + off, ah[tm]);
            }
#pragma unroll
            for (int u = 0; u < 4; u++) {
                int br = wn * 64 + u * 16 + (lane & 15);
                uint32_t off = sw128((uint32_t)(br * 128 + koff));
                uint32_t bh[4];
                ldsm4(bHs + off, bh);
#pragma unroll
                for (int tm = 0; tm < 4; tm++) {
                    mma16816(acc[tm][2*u],   ah[tm], bh[0], bh[2]);
                    mma16816(acc[tm][2*u+1], ah[tm], bh[1], bh[3]);
                }
            }
        }
        if (pre) CPC();
    }

    // ---- epilogue ----
#pragma unroll
    for (int tm = 0; tm < 4; tm++) {
#pragma unroll
        for (int j = 0; j < 8; j++) {
            int nb = n0 + wn * 64 + j * 8 + (lane & 3) * 2;
            float2 bv = *(const float2*)&bias[nb];
#pragma unroll
            for (int half = 0; half < 2; half++) {
                int m = m0 + wm * 64 + tm * 16 + (lane >> 2) + half * 8;
                float v0 = acc[tm][j][half * 2 + 0] + bv.x;
                float v1 = acc[tm][j][half * 2 + 1] + bv.y;
                if (MODE == 0) {
                    int bb = m >> 11, nn = m & (N_ - 1);
                    int which = nb >> 10, e = nb & 1023;
                    int h = e >> 6, d = e & 63;
                    size_t idx = (((size_t)bb * H_ + h) * N_ + nn) * D_ + d;
                    if (which == 0) {
                        *(uint32_t*)&g_qh[idx] = pack_h2(v0 * SCALE_, v1 * SCALE_);
                    } else if (which == 1) {
                        *(uint32_t*)&g_kh[idx] = pack_h2(v0, v1);
                    } else {
                        *(uint32_t*)&g_vh[idx] = pack_h2(v0, v1);
                    }
                } else {
                    float2 v = {v0, v1};
                    *(float2*)&C[(size_t)m * Nout + nb] = v;
                }
            }
        }
    }
}

// =====================================================================
// Flash attention, fp16 1-term both GEMMs, fp32 acc:
//   S  = qh*kh     O += Ph*Vh
// Block = 128 threads (4 warps), q-tile 64 rows, D=64.
// smem: Ph/Qh(8K) + 2 stages x (Kh,Vh) (32KB). 3 CTAs/SM.
// Heavy q-tiles launch first (reversed blockIdx).
// =====================================================================
#define AKV_STAGE 16384
#define ATT_SMEM (1024 + 8192 + 2 * AKV_STAGE)

__global__ __launch_bounds__(128, 3)
void attention_kernel()
{
    char* sm = (char*)(((uintptr_t)dyn_smem + 1023) & ~(uintptr_t)1023);
    uint32_t sb = smem_u32(sm);
    const uint32_t Pha = sb;           // P hi (mainloop) / Q hi (prologue)
    const uint32_t KVb = sb + 8192;    // stage s: Kh, Vh (8KB each)

    int tid = threadIdx.x;
    int lane = tid & 31;
    int wid = tid >> 5;
    int qt = gridDim.x - 1 - blockIdx.x;   // heavy tiles first
    int bh = blockIdx.y;
    size_t base = (size_t)bh * N_ * D_;

    // prologue: Q tile + first K/V stage
#pragma unroll
    for (int l = 0; l < 4; l++) {
        int idx = tid + l * 128;
        int row = idx >> 3, seg = idx & 7;
        size_t go = base + (size_t)(qt * 64 + row) * D_ + seg * 8;
        uint32_t off = sw128((uint32_t)(row * 128 + seg * 16));
        cpa16(Pha + off, g_qh + go);
    }
    CPC();

    auto load_kv = [&](int s, int kt) {
        uint32_t kvb = KVb + s * AKV_STAGE;
#pragma unroll
        for (int l = 0; l < 4; l++) {
            int idx = tid + l * 128;
            int row = idx >> 3, seg = idx & 7;
            size_t go = base + (size_t)(kt * 64 + row) * D_ + seg * 8;
            uint32_t off = sw128((uint32_t)(row * 128 + seg * 16));
            cpa16(kvb + off, g_kh + go);
            cpa16(kvb + 8192 + off, g_vh + go);
        }
        CPC();
    };
    load_kv(0, 0);

    CPW(0);
    __syncthreads();

    // Q fragments (pre-scaled by SCALE_)
    uint32_t qh[4][4];
    int ar = wid * 16 + (lane & 15);
#pragma unroll
    for (int ks = 0; ks < 4; ks++) {
        uint32_t off = sw128((uint32_t)(ar * 128 + (ks * 16 + (lane >> 4) * 8) * 2));
        ldsm4(Pha + off, qh[ks]);
    }

    float o[8][4];
#pragma unroll
    for (int j = 0; j < 8; j++)
#pragma unroll
        for (int e = 0; e < 4; e++) o[j][e] = 0.f;
    float m0r = -1e30f, m1r = -1e30f, l0 = 0.f, l1 = 0.f;

    int rowl0 = wid * 16 + (lane >> 2);
    int rowl1 = rowl0 + 8;

    for (int kt = 0; kt <= qt; kt++) {
        int s = kt & 1;
        __syncthreads();
        if (kt < qt) load_kv(s ^ 1, kt + 1);
        if (kt < qt) { CPW(1); } else { CPW(0); }
        __syncthreads();

        uint32_t Kh = KVb + s * AKV_STAGE;
        uint32_t Vh = Kh + 8192;

        // ---- S = Q K^T (1-term) ----
        float sc[8][4];
#pragma unroll
        for (int j = 0; j < 8; j++)
#pragma unroll
            for (int e = 0; e < 4; e++) sc[j][e] = 0.f;

#pragma unroll
        for (int ks = 0; ks < 4; ks++) {
            int koff = (ks * 16 + (lane >> 4) * 8) * 2;
            uint32_t kh4[4][4];
#pragma unroll
            for (int u = 0; u < 4; u++) {
                int br = u * 16 + (lane & 15);
                uint32_t off = sw128((uint32_t)(br * 128 + koff));
                ldsm4(Kh + off, kh4[u]);
            }
#pragma unroll
            for (int u = 0; u < 4; u++) {
                mma16816(sc[2*u],   qh[ks], kh4[u][0], kh4[u][2]);
                mma16816(sc[2*u+1], qh[ks], kh4[u][1], kh4[u][3]);
            }
        }

        if (kt == qt) {
#pragma unroll
            for (int j = 0; j < 8; j++) {
                int c = j * 8 + (lane & 3) * 2;
                if (c     > rowl0) sc[j][0] = -1e30f;
                if (c + 1 > rowl0) sc[j][1] = -1e30f;
                if (c     > rowl1) sc[j][2] = -1e30f;
                if (c + 1 > rowl1) sc[j][3] = -1e30f;
            }
        }

        // ---- online softmax ----
        float t0 = -1e30f, t1 = -1e30f;
#pragma unroll
        for (int j = 0; j < 8; j++) {
            t0 = fmaxf(t0, fmaxf(sc[j][0], sc[j][1]));
            t1 = fmaxf(t1, fmaxf(sc[j][2], sc[j][3]));
        }
        t0 = fmaxf(t0, __shfl_xor_sync(0xffffffff, t0, 1));
        t0 = fmaxf(t0, __shfl_xor_sync(0xffffffff, t0, 2));
        t1 = fmaxf(t1, __shfl_xor_sync(0xffffffff, t1, 1));
        t1 = fmaxf(t1, __shfl_xor_sync(0xffffffff, t1, 2));
        float nm0 = fmaxf(m0r, t0), nm1 = fmaxf(m1r, t1);
        float f0 = __expf(m0r - nm0), f1 = __expf(m1r - nm1);
        m0r = nm0; m1r = nm1;

        float s0 = 0.f, s1 = 0.f;
#pragma unroll
        for (int j = 0; j < 8; j++) {
            float p0 = __expf(sc[j][0] - nm0);
            float p1 = __expf(sc[j][1] - nm0);
            float p2 = __expf(sc[j][2] - nm1);
            float p3 = __expf(sc[j][3] - nm1);
            s0 += p0 + p1; s1 += p2 + p3;
            uint32_t coff = (uint32_t)(j * 16 + (lane & 3) * 4);
            uint32_t off0 = sw128((uint32_t)(rowl0 * 128) + coff);
            uint32_t off1 = sw128((uint32_t)(rowl1 * 128) + coff);
            *(uint32_t*)(sm + off0) = pack_h2(p0, p1);
            *(uint32_t*)(sm + off1) = pack_h2(p2, p3);
            o[j][0] *= f0; o[j][1] *= f0; o[j][2] *= f1; o[j][3] *= f1;
        }
        s0 += __shfl_xor_sync(0xffffffff, s0, 1);
        s0 += __shfl_xor_sync(0xffffffff, s0, 2);
        s1 += __shfl_xor_sync(0xffffffff, s1, 1);
        s1 += __shfl_xor_sync(0xffffffff, s1, 2);
        l0 = l0 * f0 + s0;
        l1 = l1 * f1 + s1;
        __syncwarp();      // P writes (warp-local rows) visible before ldsm

        // ---- O += P V (1-term) ----
#pragma unroll
        for (int ks = 0; ks < 4; ks++) {
            uint32_t offp = sw128((uint32_t)(ar * 128 + (ks * 16 + (lane >> 4) * 8) * 2));
            uint32_t ph4[4];
            ldsm4(Pha + offp, ph4);
            uint32_t vh4[4][4];
#pragma unroll
            for (int u = 0; u < 4; u++) {
                int vr = ks * 16 + ((lane >> 4) << 3) + (lane & 7);
                int vc = u * 16 + ((lane >> 3) & 1) * 8;
                uint32_t offv = sw128((uint32_t)(vr * 128 + vc * 2));
                ldsm4t(Vh + offv, vh4[u]);
            }
#pragma unroll
            for (int u = 0; u < 4; u++) {
                mma16816(o[2*u],   ph4, vh4[u][0], vh4[u][2]);
                mma16816(o[2*u+1], ph4, vh4[u][1], vh4[u][3]);
            }
        }
    }

    // ---- epilogue: normalize + write fp16 [B,N,E] ----
    float inv0 = 1.f / l0, inv1 = 1.f / l1;
    int b = bh >> 4, h = bh & 15;
    int n0g = qt * 64 + rowl0;
#pragma unroll
    for (int j = 0; j < 8; j++) {
        int d = h * 64 + j * 8 + (lane & 3) * 2;
        size_t i0 = ((size_t)b * N_ + n0g) * E_ + d;
        size_t i1 = ((size_t)b * N_ + n0g + 8) * E_ + d;
        *(uint32_t*)&g_at_hi[i0] = pack_h2(o[j][0] * inv0, o[j][1] * inv0);
        *(uint32_t*)&g_at_hi[i1] = pack_h2(o[j][2] * inv1, o[j][3] * inv1);
    }
}

// =====================================================================
// launch
// =====================================================================
extern "C" void kernel_launch(void* const* d_in, const int* in_sizes, int n_in,
                              void* d_out, int out_size)
{
    const float* x     = (const float*)d_in[0];
    const float* qkv_w = (const float*)d_in[1];
    const float* qkv_b = (const float*)d_in[2];
    const float* out_w = (const float*)d_in[3];
    const float* out_b = (const float*)d_in[4];
    float* out = (float*)d_out;

    const int M = B_ * N_;
    const int gemm_smem = 2 * GT_STAGE + 1024;   // 97 KB

    cudaFuncSetAttribute(gemm_mma<0>, cudaFuncAttributeMaxDynamicSharedMemorySize, gemm_smem);
    cudaFuncSetAttribute(gemm_mma<1>, cudaFuncAttributeMaxDynamicSharedMemorySize, gemm_smem);
    cudaFuncSetAttribute(attention_kernel, cudaFuncAttributeMaxDynamicSharedMemorySize, ATT_SMEM);

    split_kernel<0><<<(M * E_ / 4 + 255) / 256, 256>>>(x, M * E_ / 4);
    split_kernel<1><<<(3 * E_ * E_ / 4 + 255) / 256, 256>>>(qkv_w, 3 * E_ * E_ / 4);
    split_kernel<2><<<(E_ * E_ / 4 + 255) / 256, 256>>>(out_w, E_ * E_ / 4);

    gemm_mma<0><<<dim3(3 * E_ / 256, M / 128), 256, gemm_smem>>>(qkv_b, nullptr, E_, 3 * E_);

    attention_kernel<<<dim3(N_ / 64, B_ * H_), 128, ATT_SMEM>>>();

    gemm_mma<1><<<dim3(E_ / 256, M / 128), 256, gemm_smem>>>(out_b, out, E_, E_);
}

// round 16
// speedup vs baseline: 1.7944x; 1.0006x over previous
#include <cuda_runtime.h>
#include <cuda_fp16.h>
#include <cstdint>

// ---------------- problem constants ----------------
#define B_   2
#define N_   2048
#define E_   1024
#define H_   16
#define D_   64
#define SCALE_ 0.125f   // 64^-0.5

// ---------------- device scratch (no allocs allowed) ----------------
__device__ __half g_x_hi[(size_t)B_*N_*E_];            // x rounded
__device__ __half g_w_hi[(size_t)3*E_*E_];             // qkv_w rounded
__device__ __half g_ow_hi[(size_t)E_*E_];              // out_w rounded
__device__ __half g_qh[(size_t)B_*H_*N_*D_];           // rounded, pre-scaled by SCALE_
__device__ __half g_kh[(size_t)B_*H_*N_*D_];           // rounded (S 1-term)
__device__ __half g_vh[(size_t)B_*H_*N_*D_];           // rounded (PV 1-term)
__device__ __half g_at_hi[(size_t)B_*N_*E_];           // attention out rounded

// =====================================================================
// helpers
// =====================================================================
__device__ __forceinline__ uint32_t smem_u32(const void* p) {
    uint32_t a;
    asm("{ .reg .u64 t; cvta.to.shared.u64 t, %1; cvt.u32.u64 %0, t; }" : "=r"(a) : "l"(p));
    return a;
}
__device__ __forceinline__ uint32_t sw128(uint32_t off) { return off ^ ((off >> 3) & 0x70); }

__device__ __forceinline__ void cpa16(uint32_t dst, const void* src) {
    asm volatile("cp.async.cg.shared.global [%0], [%1], 16;" :: "r"(dst), "l"(src));
}
#define CPC() asm volatile("cp.async.commit_group;" ::: "memory")
#define CPW(n) asm volatile("cp.async.wait_group %0;" :: "n"(n) : "memory")

__device__ __forceinline__ void ldsm4(uint32_t addr, uint32_t* r) {
    asm volatile("ldmatrix.sync.aligned.m8n8.x4.shared.b16 {%0,%1,%2,%3}, [%4];"
        : "=r"(r[0]), "=r"(r[1]), "=r"(r[2]), "=r"(r[3]) : "r"(addr));
}
__device__ __forceinline__ void ldsm4t(uint32_t addr, uint32_t* r) {
    asm volatile("ldmatrix.sync.aligned.m8n8.x4.trans.shared.b16 {%0,%1,%2,%3}, [%4];"
        : "=r"(r[0]), "=r"(r[1]), "=r"(r[2]), "=r"(r[3]) : "r"(addr));
}
// fp16 in, fp32 accumulate
__device__ __forceinline__ void mma16816(float* c, const uint32_t* a, uint32_t b0, uint32_t b1) {
    asm("mma.sync.aligned.m16n8k16.row.col.f32.f16.f16.f32 "
        "{%0,%1,%2,%3},{%4,%5,%6,%7},{%8,%9},{%0,%1,%2,%3};"
        : "+f"(c[0]), "+f"(c[1]), "+f"(c[2]), "+f"(c[3])
        : "r"(a[0]), "r"(a[1]), "r"(a[2]), "r"(a[3]), "r"(b0), "r"(b1));
}

__device__ __forceinline__ uint32_t pack_h2(float v0, float v1) {
    __half2 h = __floats2half2_rn(v0, v1);
    return *(uint32_t*)&h;
}

// =====================================================================
// merged split kernel: converts x, qkv_w, out_w fp32 -> fp16 in ONE launch
// =====================================================================
#define X4_  (B_*N_*E_/4)        // 1048576
#define W4_  (3*E_*E_/4)         // 786432
#define OW4_ (E_*E_/4)           // 262144

__global__ void split_all(const float* __restrict__ x,
                          const float* __restrict__ w,
                          const float* __restrict__ ow)
{
    int i = blockIdx.x * blockDim.x + threadIdx.x;
    const float* src;
    __half* dst;
    int j;
    if (i < X4_)            { src = x;  dst = g_x_hi;  j = i; }
    else if (i < X4_ + W4_) { src = w;  dst = g_w_hi;  j = i - X4_; }
    else if (i < X4_ + W4_ + OW4_) { src = ow; dst = g_ow_hi; j = i - X4_ - W4_; }
    else return;
    float4 a = *(const float4*)&src[(size_t)j * 4];
    uint2 hv = {pack_h2(a.x, a.y), pack_h2(a.z, a.w)};
    *(uint2*)&dst[(size_t)j * 4] = hv;
}

// =====================================================================
// mma.sync GEMM (NT), fp16 1-term, fp32 acc:
// BM=128, BN=256, BK=64. 256 threads, 8 warps (2x4), warp tile 64x64.
// MODE 0: epilogue -> q/k/v (rounded) scatter [B,H,N,D], q scaled.
// MODE 1: fp32 C row-major.
// =====================================================================
#define GA_TILE 16384                // A: 128 rows * 128B
#define GB_TILE 32768                // B: 256 rows * 128B
#define GT_STAGE (GA_TILE + GB_TILE) // 48KB

extern __shared__ __align__(16) char dyn_smem[];

template<int MODE>
__global__ __launch_bounds__(256, 1)
void gemm_mma(const float* __restrict__ bias, float* __restrict__ C, int K, int Nout)
{
    const __half* Ah = (MODE == 0) ? g_x_hi : g_at_hi;
    const __half* Bh = (MODE == 0) ? g_w_hi : g_ow_hi;

    char* sm = (char*)(((uintptr_t)dyn_smem + 1023) & ~(uintptr_t)1023);
    uint32_t sb = smem_u32(sm);

    int tid = threadIdx.x;
    int lane = tid & 31;
    int wid = tid >> 5;
    int wm = wid >> 2;
    int wn = wid & 3;
    int m0 = blockIdx.y * 128;
    int n0 = blockIdx.x * 256;

    float acc[4][8][4];
#pragma unroll
    for (int a = 0; a < 4; a++)
#pragma unroll
        for (int b = 0; b < 8; b++)
#pragma unroll
            for (int c = 0; c < 4; c++) acc[a][b][c] = 0.f;

    auto load_quarter = [&](int s, int k0, int q) {
        uint32_t st = sb + s * GT_STAGE;
        {
            int idx = tid + q * 256;
            int row = idx >> 3, seg = idx & 7;
            uint32_t off = sw128((uint32_t)(row * 128 + seg * 16));
            size_t go = (size_t)(m0 + row) * K + k0 + seg * 8;
            cpa16(st + off, Ah + go);
        }
#pragma unroll
        for (int l2 = 0; l2 < 2; l2++) {
            int idx = tid + (q * 2 + l2) * 256;
            int row = idx >> 3, seg = idx & 7;
            uint32_t off = sw128((uint32_t)(row * 128 + seg * 16));
            size_t go = (size_t)(n0 + row) * K + k0 + seg * 8;
            cpa16(st + GA_TILE + off, Bh + go);
        }
    };

    const int NIT = K / 64;
#pragma unroll
    for (int q = 0; q < 4; q++) load_quarter(0, 0, q);
    CPC();

    for (int it = 0; it < NIT; it++) {
        int s = it & 1;
        CPW(0);
        __syncthreads();

        uint32_t aH = sb + s * GT_STAGE;
        uint32_t bHs = aH + GA_TILE;
        bool pre = (it + 1 < NIT);

#pragma unroll
        for (int ks = 0; ks < 4; ks++) {
            if (pre) load_quarter(s ^ 1, (it + 1) * 64, ks);

            int koff = (ks * 16 + (lane >> 4) * 8) * 2;
            uint32_t ah[4][4];
#pragma unroll
            for (int tm = 0; tm < 4; tm++) {
                int ar = wm * 64 + tm * 16 + (lane & 15);
                uint32_t off = sw128((uint32_t)(ar * 128 + koff));
                ldsm4(aH + off, ah[tm]);
            }
#pragma unroll
            for (int u = 0; u < 4; u++) {
                int br = wn * 64 + u * 16 + (lane & 15);
                uint32_t off = sw128((uint32_t)(br * 128 + koff));
                uint32_t bh[4];
                ldsm4(bHs + off, bh);
#pragma unroll
                for (int tm = 0; tm < 4; tm++) {
                    mma16816(acc[tm][2*u],   ah[tm], bh[0], bh[2]);
                    mma16816(acc[tm][2*u+1], ah[tm], bh[1], bh[3]);
                }
            }
        }
        if (pre) CPC();
    }

    // ---- epilogue ----
#pragma unroll
    for (int tm = 0; tm < 4; tm++) {
#pragma unroll
        for (int j = 0; j < 8; j++) {
            int nb = n0 + wn * 64 + j * 8 + (lane & 3) * 2;
            float2 bv = *(const float2*)&bias[nb];
#pragma unroll
            for (int half = 0; half < 2; half++) {
                int m = m0 + wm * 64 + tm * 16 + (lane >> 2) + half * 8;
                float v0 = acc[tm][j][half * 2 + 0] + bv.x;
                float v1 = acc[tm][j][half * 2 + 1] + bv.y;
                if (MODE == 0) {
                    int bb = m >> 11, nn = m & (N_ - 1);
                    int which = nb >> 10, e = nb & 1023;
                    int h = e >> 6, d = e & 63;
                    size_t idx = (((size_t)bb * H_ + h) * N_ + nn) * D_ + d;
                    if (which == 0) {
                        *(uint32_t*)&g_qh[idx] = pack_h2(v0 * SCALE_, v1 * SCALE_);
                    } else if (which == 1) {
                        *(uint32_t*)&g_kh[idx] = pack_h2(v0, v1);
                    } else {
                        *(uint32_t*)&g_vh[idx] = pack_h2(v0, v1);
                    }
                } else {
                    float2 v = {v0, v1};
                    *(float2*)&C[(size_t)m * Nout + nb] = v;
                }
            }
        }
    }
}

// =====================================================================
// Flash attention, fp16 1-term, K-TILE 128 (halved softmax/sync passes):
//   S = qh*kh ; O += Ph*Vh
// Block = 128 threads (4 warps), q-tile 64 rows, k-tile 128, D=64.
// smem: P (2 x 8KB subtiles, 64 keys each) + 2 stages x (Kh 16KB, Vh 16KB).
// P/Q region reused. 2 CTAs/SM.
// =====================================================================
#define AKV_STAGE 32768            // Kh(16K) + Vh(16K)
#define ATT_SMEM (1024 + 16384 + 2 * AKV_STAGE)

__global__ __launch_bounds__(128, 2)
void attention_kernel()
{
    char* sm = (char*)(((uintptr_t)dyn_smem + 1023) & ~(uintptr_t)1023);
    uint32_t sb = smem_u32(sm);
    const uint32_t Pa  = sb;            // keys 0-63 subtile (8KB); Q during prologue
    const uint32_t Pb  = sb + 8192;     // keys 64-127 subtile (8KB)
    const uint32_t KVb = sb + 16384;    // stage s: Kh(16KB), Vh(16KB)

    int tid = threadIdx.x;
    int lane = tid & 31;
    int wid = tid >> 5;
    int qt = gridDim.x - 1 - blockIdx.x;   // heavy tiles first
    int bh = blockIdx.y;
    size_t base = (size_t)bh * N_ * D_;

    // prologue: Q tile (64x64 fp16, 8KB) into Pa
#pragma unroll
    for (int l = 0; l < 4; l++) {
        int idx = tid + l * 128;
        int row = idx >> 3, seg = idx & 7;
        size_t go = base + (size_t)(qt * 64 + row) * D_ + seg * 8;
        uint32_t off = sw128((uint32_t)(row * 128 + seg * 16));
        cpa16(Pa + off, g_qh + go);
    }
    CPC();

    // load 128-key K/V stage (rows kt*128 .. kt*128+127)
    auto load_kv = [&](int s, int kt) {
        uint32_t kvb = KVb + s * AKV_STAGE;
#pragma unroll
        for (int l = 0; l < 8; l++) {
            int idx = tid + l * 128;           // 0..1023
            int row = idx >> 3, seg = idx & 7; // 128 rows x 8 segs
            size_t go = base + (size_t)(kt * 128 + row) * D_ + seg * 8;
            uint32_t off = sw128((uint32_t)(row * 128 + seg * 16));
            cpa16(kvb + off, g_kh + go);
            cpa16(kvb + 16384 + off, g_vh + go);
        }
        CPC();
    };
    load_kv(0, 0);

    CPW(0);
    __syncthreads();

    // Q fragments (pre-scaled by SCALE_)
    uint32_t qh[4][4];
    int ar = wid * 16 + (lane & 15);
#pragma unroll
    for (int ks = 0; ks < 4; ks++) {
        uint32_t off = sw128((uint32_t)(ar * 128 + (ks * 16 + (lane >> 4) * 8) * 2));
        ldsm4(Pa + off, qh[ks]);
    }

    float o[8][4];
#pragma unroll
    for (int j = 0; j < 8; j++)
#pragma unroll
        for (int e = 0; e < 4; e++) o[j][e] = 0.f;
    float m0r = -1e30f, m1r = -1e30f, l0 = 0.f, l1 = 0.f;

    int rowl0 = wid * 16 + (lane >> 2);
    int rowl1 = rowl0 + 8;
    int grow0 = qt * 64 + rowl0;
    int grow1 = qt * 64 + rowl1;

    // number of 128-key tiles covering keys [0, qt*64+64)
    const int NKT = (qt * 64 + 64 + 127) / 128;

    for (int kt = 0; kt < NKT; kt++) {
        int s = kt & 1;
        __syncthreads();
        if (kt + 1 < NKT) load_kv(s ^ 1, kt + 1);
        if (kt + 1 < NKT) { CPW(1); } else { CPW(0); }
        __syncthreads();

        uint32_t Kh = KVb + s * AKV_STAGE;
        uint32_t Vh = Kh + 16384;

        // ---- S = Q K^T (64 rows x 128 keys, 1-term) ----
        float sc[16][4];
#pragma unroll
        for (int j = 0; j < 16; j++)
#pragma unroll
            for (int e = 0; e < 4; e++) sc[j][e] = 0.f;

#pragma unroll
        for (int ks = 0; ks < 4; ks++) {
            int koff = (ks * 16 + (lane >> 4) * 8) * 2;
#pragma unroll
            for (int u = 0; u < 8; u++) {
                int br = u * 16 + (lane & 15);
                uint32_t off = sw128((uint32_t)(br * 128 + koff));
                uint32_t kh4[4];
                ldsm4(Kh + off, kh4);
                mma16816(sc[2*u],   qh[ks], kh4[0], kh4[2]);
                mma16816(sc[2*u+1], qh[ks], kh4[1], kh4[3]);
            }
        }

        // causal mask on the diagonal-straddling (last) tile
        if (kt == NKT - 1) {
#pragma unroll
            for (int j = 0; j < 16; j++) {
                int c = kt * 128 + j * 8 + (lane & 3) * 2;
                if (c     > grow0) sc[j][0] = -1e30f;
                if (c + 1 > grow0) sc[j][1] = -1e30f;
                if (c     > grow1) sc[j][2] = -1e30f;
                if (c + 1 > grow1) sc[j][3] = -1e30f;
            }
        }

        // ---- online softmax (one pass per 128 keys) ----
        float t0 = -1e30f, t1 = -1e30f;
#pragma unroll
        for (int j = 0; j < 16; j++) {
            t0 = fmaxf(t0, fmaxf(sc[j][0], sc[j][1]));
            t1 = fmaxf(t1, fmaxf(sc[j][2], sc[j][3]));
        }
        t0 = fmaxf(t0, __shfl_xor_sync(0xffffffff, t0, 1));
        t0 = fmaxf(t0, __shfl_xor_sync(0xffffffff, t0, 2));
        t1 = fmaxf(t1, __shfl_xor_sync(0xffffffff, t1, 1));
        t1 = fmaxf(t1, __shfl_xor_sync(0xffffffff, t1, 2));
        float nm0 = fmaxf(m0r, t0), nm1 = fmaxf(m1r, t1);
        float f0 = __expf(m0r - nm0), f1 = __expf(m1r - nm1);
        m0r = nm0; m1r = nm1;

        float s0 = 0.f, s1 = 0.f;
#pragma unroll
        for (int j = 0; j < 16; j++) {
            float p0 = __expf(sc[j][0] - nm0);
            float p1 = __expf(sc[j][1] - nm0);
            float p2 = __expf(sc[j][2] - nm1);
            float p3 = __expf(sc[j][3] - nm1);
            s0 += p0 + p1; s1 += p2 + p3;
            // P subtile select: keys j*8.. -> j<8 => Pa, j>=8 => Pb
            uint32_t pb = (j < 8) ? Pa : Pb;
            uint32_t coff = (uint32_t)((j & 7) * 16 + (lane & 3) * 4);
            uint32_t off0 = sw128((uint32_t)(rowl0 * 128) + coff);
            uint32_t off1 = sw128((uint32_t)(rowl1 * 128) + coff);
            *(uint32_t*)(sm + (pb - sb) + off0) = pack_h2(p0, p1);
            *(uint32_t*)(sm + (pb - sb) + off1) = pack_h2(p2, p3);
        }
#pragma unroll
        for (int j = 0; j < 8; j++) {
            o[j][0] *= f0; o[j][1] *= f0; o[j][2] *= f1; o[j][3] *= f1;
        }
        s0 += __shfl_xor_sync(0xffffffff, s0, 1);
        s0 += __shfl_xor_sync(0xffffffff, s0, 2);
        s1 += __shfl_xor_sync(0xffffffff, s1, 1);
        s1 += __shfl_xor_sync(0xffffffff, s1, 2);
        l0 = l0 * f0 + s0;
        l1 = l1 * f1 + s1;
        __syncwarp();      // P writes (warp-local rows) visible before ldsm

        // ---- O += P V (128-deep, 1-term) ----
#pragma unroll
        for (int ks = 0; ks < 8; ks++) {
            uint32_t pbase = (ks < 4) ? Pa : Pb;
            int ksl = ks & 3;
            uint32_t offp = sw128((uint32_t)(ar * 128 + (ksl * 16 + (lane >> 4) * 8) * 2));
            uint32_t ph4[4];
            ldsm4(pbase + offp, ph4);
            uint32_t vh4[4][4];
#pragma unroll
            for (int u = 0; u < 4; u++) {
                int vr = ks * 16 + ((lane >> 4) << 3) + (lane & 7);
                int vc = u * 16 + ((lane >> 3) & 1) * 8;
                uint32_t offv = sw128((uint32_t)(vr * 128 + vc * 2));
                ldsm4t(Vh + offv, vh4[u]);
            }
#pragma unroll
            for (int u = 0; u < 4; u++) {
                mma16816(o[2*u],   ph4, vh4[u][0], vh4[u][2]);
                mma16816(o[2*u+1], ph4, vh4[u][1], vh4[u][3]);
            }
        }
    }

    // ---- epilogue: normalize + write fp16 [B,N,E] ----
    float inv0 = 1.f / l0, inv1 = 1.f / l1;
    int b = bh >> 4, h = bh & 15;
#pragma unroll
    for (int j = 0; j < 8; j++) {
        int d = h * 64 + j * 8 + (lane & 3) * 2;
        size_t i0 = ((size_t)b * N_ + grow0) * E_ + d;
        size_t i1 = ((size_t)b * N_ + grow1) * E_ + d;
        *(uint32_t*)&g_at_hi[i0] = pack_h2(o[j][0] * inv0, o[j][1] * inv0);
        *(uint32_t*)&g_at_hi[i1] = pack_h2(o[j][2] * inv1, o[j][3] * inv1);
    }
}

// =====================================================================
// launch
// =====================================================================
extern "C" void kernel_launch(void* const* d_in, const int* in_sizes, int n_in,
                              void* d_out, int out_size)
{
    const float* x     = (const float*)d_in[0];
    const float* qkv_w = (const float*)d_in[1];
    const float* qkv_b = (const float*)d_in[2];
    const float* out_w = (const float*)d_in[3];
    const float* out_b = (const float*)d_in[4];
    float* out = (float*)d_out;

    const int M = B_ * N_;
    const int gemm_smem = 2 * GT_STAGE + 1024;   // 97 KB

    cudaFuncSetAttribute(gemm_mma<0>, cudaFuncAttributeMaxDynamicSharedMemorySize, gemm_smem);
    cudaFuncSetAttribute(gemm_mma<1>, cudaFuncAttributeMaxDynamicSharedMemorySize, gemm_smem);
    cudaFuncSetAttribute(attention_kernel, cudaFuncAttributeMaxDynamicSharedMemorySize, ATT_SMEM);

    // 1) one merged split launch (x, qkv_w, out_w -> fp16)
    {
        int total = X4_ + W4_ + OW4_;
        split_all<<<(total + 255) / 256, 256>>>(x, qkv_w, out_w);
    }

    // 2) QKV projection -> q/k/v fp16 [B,H,N,D]
    gemm_mma<0><<<dim3(3 * E_ / 256, M / 128), 256, gemm_smem>>>(qkv_b, nullptr, E_, 3 * E_);

    // 3) causal flash attention -> g_at_hi [B,N,E]
    attention_kernel<<<dim3(N_ / 64, B_ * H_), 128, ATT_SMEM>>>();

    // 4) output projection -> out (fp32)
    gemm_mma<1><<<dim3(E_ / 256, M / 128), 256, gemm_smem>>>(out_b, out, E_, E_);
}

// round 17
// speedup vs baseline: 1.8323x; 1.0211x over previous
#include <cuda_runtime.h>
#include <cuda_fp16.h>
#include <cstdint>

// ---------------- problem constants ----------------
#define B_   2
#define N_   2048
#define E_   1024
#define H_   16
#define D_   64
#define SCALE_ 0.125f   // 64^-0.5

// ---------------- device scratch (no allocs allowed) ----------------
__device__ __half g_x_hi[(size_t)B_*N_*E_];            // x rounded
__device__ __half g_w_hi[(size_t)3*E_*E_];             // qkv_w rounded
__device__ __half g_ow_hi[(size_t)E_*E_];              // out_w rounded
__device__ __half g_qh[(size_t)B_*H_*N_*D_];           // rounded, pre-scaled by SCALE_
__device__ __half g_kh[(size_t)B_*H_*N_*D_];           // rounded (S 1-term)
__device__ __half g_vh[(size_t)B_*H_*N_*D_];           // rounded (PV 1-term)
__device__ __half g_at_hi[(size_t)B_*N_*E_];           // attention out rounded

// =====================================================================
// helpers
// =====================================================================
__device__ __forceinline__ uint32_t smem_u32(const void* p) {
    uint32_t a;
    asm("{ .reg .u64 t; cvta.to.shared.u64 t, %1; cvt.u32.u64 %0, t; }" : "=r"(a) : "l"(p));
    return a;
}
__device__ __forceinline__ uint32_t sw128(uint32_t off) { return off ^ ((off >> 3) & 0x70); }

__device__ __forceinline__ void cpa16(uint32_t dst, const void* src) {
    asm volatile("cp.async.cg.shared.global [%0], [%1], 16;" :: "r"(dst), "l"(src));
}
#define CPC() asm volatile("cp.async.commit_group;" ::: "memory")
#define CPW(n) asm volatile("cp.async.wait_group %0;" :: "n"(n) : "memory")

__device__ __forceinline__ void ldsm4(uint32_t addr, uint32_t* r) {
    asm volatile("ldmatrix.sync.aligned.m8n8.x4.shared.b16 {%0,%1,%2,%3}, [%4];"
        : "=r"(r[0]), "=r"(r[1]), "=r"(r[2]), "=r"(r[3]) : "r"(addr));
}
__device__ __forceinline__ void ldsm4t(uint32_t addr, uint32_t* r) {
    asm volatile("ldmatrix.sync.aligned.m8n8.x4.trans.shared.b16 {%0,%1,%2,%3}, [%4];"
        : "=r"(r[0]), "=r"(r[1]), "=r"(r[2]), "=r"(r[3]) : "r"(addr));
}
// fp16 in, fp32 accumulate
__device__ __forceinline__ void mma16816(float* c, const uint32_t* a, uint32_t b0, uint32_t b1) {
    asm("mma.sync.aligned.m16n8k16.row.col.f32.f16.f16.f32 "
        "{%0,%1,%2,%3},{%4,%5,%6,%7},{%8,%9},{%0,%1,%2,%3};"
        : "+f"(c[0]), "+f"(c[1]), "+f"(c[2]), "+f"(c[3])
        : "r"(a[0]), "r"(a[1]), "r"(a[2]), "r"(a[3]), "r"(b0), "r"(b1));
}

__device__ __forceinline__ uint32_t pack_h2(float v0, float v1) {
    __half2 h = __floats2half2_rn(v0, v1);
    return *(uint32_t*)&h;
}

// =====================================================================
// merged split kernel: converts x, qkv_w, out_w fp32 -> fp16 in ONE launch
// =====================================================================
#define X4_  (B_*N_*E_/4)        // 1048576
#define W4_  (3*E_*E_/4)         // 786432
#define OW4_ (E_*E_/4)           // 262144

__global__ void split_all(const float* __restrict__ x,
                          const float* __restrict__ w,
                          const float* __restrict__ ow)
{
    int i = blockIdx.x * blockDim.x + threadIdx.x;
    const float* src;
    __half* dst;
    int j;
    if (i < X4_)            { src = x;  dst = g_x_hi;  j = i; }
    else if (i < X4_ + W4_) { src = w;  dst = g_w_hi;  j = i - X4_; }
    else if (i < X4_ + W4_ + OW4_) { src = ow; dst = g_ow_hi; j = i - X4_ - W4_; }
    else return;
    float4 a = *(const float4*)&src[(size_t)j * 4];
    uint2 hv = {pack_h2(a.x, a.y), pack_h2(a.z, a.w)};
    *(uint2*)&dst[(size_t)j * 4] = hv;
}

// =====================================================================
// mma.sync GEMM (NT), fp16 1-term, fp32 acc — 2 CTAs/SM config:
// BM=128, BN=128, BK=64. 256 threads, 8 warps (2x4), warp tile 64x32.
// smem stage: Ah(16K)+Bh(16K)=32KB, double buffered = 65KB -> 2 CTAs/SM.
// MODE 0: epilogue -> q/k/v (rounded) scatter [B,H,N,D], q scaled.
// MODE 1: fp32 C row-major.
// =====================================================================
#define GA_TILE 16384                // A: 128 rows * 128B
#define GB_TILE 16384                // B: 128 rows * 128B
#define GT_STAGE (GA_TILE + GB_TILE) // 32KB

extern __shared__ __align__(16) char dyn_smem[];

template<int MODE>
__global__ __launch_bounds__(256, 2)
void gemm_mma(const float* __restrict__ bias, float* __restrict__ C, int K, int Nout)
{
    const __half* Ah = (MODE == 0) ? g_x_hi : g_at_hi;
    const __half* Bh = (MODE == 0) ? g_w_hi : g_ow_hi;

    char* sm = (char*)(((uintptr_t)dyn_smem + 1023) & ~(uintptr_t)1023);
    uint32_t sb = smem_u32(sm);

    int tid = threadIdx.x;
    int lane = tid & 31;
    int wid = tid >> 5;
    int wm = wid >> 2;               // 0..1 -> rows wm*64
    int wn = wid & 3;                // 0..3 -> cols wn*32
    int m0 = blockIdx.y * 128;
    int n0 = blockIdx.x * 128;

    float acc[4][4][4];
#pragma unroll
    for (int a = 0; a < 4; a++)
#pragma unroll
        for (int b = 0; b < 4; b++)
#pragma unroll
            for (int c = 0; c < 4; c++) acc[a][b][c] = 0.f;

    // quarter q of stage loads: 1 A chunk + 1 B chunk per thread per quarter
    auto load_quarter = [&](int s, int k0, int q) {
        uint32_t st = sb + s * GT_STAGE;
        int idx = tid + q * 256;            // 0..1023
        int row = idx >> 3, seg = idx & 7;
        uint32_t off = sw128((uint32_t)(row * 128 + seg * 16));
        size_t goA = (size_t)(m0 + row) * K + k0 + seg * 8;
        size_t goB = (size_t)(n0 + row) * K + k0 + seg * 8;
        cpa16(st + off, Ah + goA);
        cpa16(st + GA_TILE + off, Bh + goB);
    };

    const int NIT = K / 64;
#pragma unroll
    for (int q = 0; q < 4; q++) load_quarter(0, 0, q);
    CPC();

    for (int it = 0; it < NIT; it++) {
        int s = it & 1;
        CPW(0);
        __syncthreads();

        uint32_t aH = sb + s * GT_STAGE;
        uint32_t bHs = aH + GA_TILE;
        bool pre = (it + 1 < NIT);

#pragma unroll
        for (int ks = 0; ks < 4; ks++) {
            if (pre) load_quarter(s ^ 1, (it + 1) * 64, ks);

            int koff = (ks * 16 + (lane >> 4) * 8) * 2;
            uint32_t ah[4][4];
#pragma unroll
            for (int tm = 0; tm < 4; tm++) {
                int ar = wm * 64 + tm * 16 + (lane & 15);
                uint32_t off = sw128((uint32_t)(ar * 128 + koff));
                ldsm4(aH + off, ah[tm]);
            }
#pragma unroll
            for (int u = 0; u < 2; u++) {
                int br = wn * 32 + u * 16 + (lane & 15);
                uint32_t off = sw128((uint32_t)(br * 128 + koff));
                uint32_t bh[4];
                ldsm4(bHs + off, bh);
#pragma unroll
                for (int tm = 0; tm < 4; tm++) {
                    mma16816(acc[tm][2*u],   ah[tm], bh[0], bh[2]);
                    mma16816(acc[tm][2*u+1], ah[tm], bh[1], bh[3]);
                }
            }
        }
        if (pre) CPC();
    }

    // ---- epilogue ----
#pragma unroll
    for (int tm = 0; tm < 4; tm++) {
#pragma unroll
        for (int j = 0; j < 4; j++) {
            int nb = n0 + wn * 32 + j * 8 + (lane & 3) * 2;
            float2 bv = *(const float2*)&bias[nb];
#pragma unroll
            for (int half = 0; half < 2; half++) {
                int m = m0 + wm * 64 + tm * 16 + (lane >> 2) + half * 8;
                float v0 = acc[tm][j][half * 2 + 0] + bv.x;
                float v1 = acc[tm][j][half * 2 + 1] + bv.y;
                if (MODE == 0) {
                    int bb = m >> 11, nn = m & (N_ - 1);
                    int which = nb >> 10, e = nb & 1023;
                    int h = e >> 6, d = e & 63;
                    size_t idx = (((size_t)bb * H_ + h) * N_ + nn) * D_ + d;
                    if (which == 0) {
                        *(uint32_t*)&g_qh[idx] = pack_h2(v0 * SCALE_, v1 * SCALE_);
                    } else if (which == 1) {
                        *(uint32_t*)&g_kh[idx] = pack_h2(v0, v1);
                    } else {
                        *(uint32_t*)&g_vh[idx] = pack_h2(v0, v1);
                    }
                } else {
                    float2 v = {v0, v1};
                    *(float2*)&C[(size_t)m * Nout + nb] = v;
                }
            }
        }
    }
}

// =====================================================================
// Flash attention, fp16 1-term, K-TILE 128 (unchanged from r16):
//   S = qh*kh ; O += Ph*Vh
// Block = 128 threads (4 warps), q-tile 64 rows, k-tile 128, D=64.
// smem: P (2 x 8KB subtiles) + 2 stages x (Kh 16KB, Vh 16KB). 2 CTAs/SM.
// =====================================================================
#define AKV_STAGE 32768            // Kh(16K) + Vh(16K)
#define ATT_SMEM (1024 + 16384 + 2 * AKV_STAGE)

__global__ __launch_bounds__(128, 2)
void attention_kernel()
{
    char* sm = (char*)(((uintptr_t)dyn_smem + 1023) & ~(uintptr_t)1023);
    uint32_t sb = smem_u32(sm);
    const uint32_t Pa  = sb;            // keys 0-63 subtile (8KB); Q during prologue
    const uint32_t Pb  = sb + 8192;     // keys 64-127 subtile (8KB)
    const uint32_t KVb = sb + 16384;    // stage s: Kh(16KB), Vh(16KB)

    int tid = threadIdx.x;
    int lane = tid & 31;
    int wid = tid >> 5;
    int qt = gridDim.x - 1 - blockIdx.x;   // heavy tiles first
    int bh = blockIdx.y;
    size_t base = (size_t)bh * N_ * D_;

    // prologue: Q tile (64x64 fp16, 8KB) into Pa
#pragma unroll
    for (int l = 0; l < 4; l++) {
        int idx = tid + l * 128;
        int row = idx >> 3, seg = idx & 7;
        size_t go = base + (size_t)(qt * 64 + row) * D_ + seg * 8;
        uint32_t off = sw128((uint32_t)(row * 128 + seg * 16));
        cpa16(Pa + off, g_qh + go);
    }
    CPC();

    // load 128-key K/V stage (rows kt*128 .. kt*128+127)
    auto load_kv = [&](int s, int kt) {
        uint32_t kvb = KVb + s * AKV_STAGE;
#pragma unroll
        for (int l = 0; l < 8; l++) {
            int idx = tid + l * 128;
            int row = idx >> 3, seg = idx & 7;
            size_t go = base + (size_t)(kt * 128 + row) * D_ + seg * 8;
            uint32_t off = sw128((uint32_t)(row * 128 + seg * 16));
            cpa16(kvb + off, g_kh + go);
            cpa16(kvb + 16384 + off, g_vh + go);
        }
        CPC();
    };
    load_kv(0, 0);

    CPW(0);
    __syncthreads();

    // Q fragments (pre-scaled by SCALE_)
    uint32_t qh[4][4];
    int ar = wid * 16 + (lane & 15);
#pragma unroll
    for (int ks = 0; ks < 4; ks++) {
        uint32_t off = sw128((uint32_t)(ar * 128 + (ks * 16 + (lane >> 4) * 8) * 2));
        ldsm4(Pa + off, qh[ks]);
    }

    float o[8][4];
#pragma unroll
    for (int j = 0; j < 8; j++)
#pragma unroll
        for (int e = 0; e < 4; e++) o[j][e] = 0.f;
    float m0r = -1e30f, m1r = -1e30f, l0 = 0.f, l1 = 0.f;

    int rowl0 = wid * 16 + (lane >> 2);
    int rowl1 = rowl0 + 8;
    int grow0 = qt * 64 + rowl0;
    int grow1 = qt * 64 + rowl1;

    const int NKT = (qt * 64 + 64 + 127) / 128;

    for (int kt = 0; kt < NKT; kt++) {
        int s = kt & 1;
        __syncthreads();
        if (kt + 1 < NKT) load_kv(s ^ 1, kt + 1);
        if (kt + 1 < NKT) { CPW(1); } else { CPW(0); }
        __syncthreads();

        uint32_t Kh = KVb + s * AKV_STAGE;
        uint32_t Vh = Kh + 16384;

        // ---- S = Q K^T (64 rows x 128 keys, 1-term) ----
        float sc[16][4];
#pragma unroll
        for (int j = 0; j < 16; j++)
#pragma unroll
            for (int e = 0; e < 4; e++) sc[j][e] = 0.f;

#pragma unroll
        for (int ks = 0; ks < 4; ks++) {
            int koff = (ks * 16 + (lane >> 4) * 8) * 2;
#pragma unroll
            for (int u = 0; u < 8; u++) {
                int br = u * 16 + (lane & 15);
                uint32_t off = sw128((uint32_t)(br * 128 + koff));
                uint32_t kh4[4];
                ldsm4(Kh + off, kh4);
                mma16816(sc[2*u],   qh[ks], kh4[0], kh4[2]);
                mma16816(sc[2*u+1], qh[ks], kh4[1], kh4[3]);
            }
        }

        // causal mask on the diagonal-straddling (last) tile
        if (kt == NKT - 1) {
#pragma unroll
            for (int j = 0; j < 16; j++) {
                int c = kt * 128 + j * 8 + (lane & 3) * 2;
                if (c     > grow0) sc[j][0] = -1e30f;
                if (c + 1 > grow0) sc[j][1] = -1e30f;
                if (c     > grow1) sc[j][2] = -1e30f;
                if (c + 1 > grow1) sc[j][3] = -1e30f;
            }
        }

        // ---- online softmax ----
        float t0 = -1e30f, t1 = -1e30f;
#pragma unroll
        for (int j = 0; j < 16; j++) {
            t0 = fmaxf(t0, fmaxf(sc[j][0], sc[j][1]));
            t1 = fmaxf(t1, fmaxf(sc[j][2], sc[j][3]));
        }
        t0 = fmaxf(t0, __shfl_xor_sync(0xffffffff, t0, 1));
        t0 = fmaxf(t0, __shfl_xor_sync(0xffffffff, t0, 2));
        t1 = fmaxf(t1, __shfl_xor_sync(0xffffffff, t1, 1));
        t1 = fmaxf(t1, __shfl_xor_sync(0xffffffff, t1, 2));
        float nm0 = fmaxf(m0r, t0), nm1 = fmaxf(m1r, t1);
        float f0 = __expf(m0r - nm0), f1 = __expf(m1r - nm1);
        m0r = nm0; m1r = nm1;

        float s0 = 0.f, s1 = 0.f;
#pragma unroll
        for (int j = 0; j < 16; j++) {
            float p0 = __expf(sc[j][0] - nm0);
            float p1 = __expf(sc[j][1] - nm0);
            float p2 = __expf(sc[j][2] - nm1);
            float p3 = __expf(sc[j][3] - nm1);
            s0 += p0 + p1; s1 += p2 + p3;
            uint32_t pb = (j < 8) ? Pa : Pb;
            uint32_t coff = (uint32_t)((j & 7) * 16 + (lane & 3) * 4);
            uint32_t off0 = sw128((uint32_t)(rowl0 * 128) + coff);
            uint32_t off1 = sw128((uint32_t)(rowl1 * 128) + coff);
            *(uint32_t*)(sm + (pb - sb) + off0) = pack_h2(p0, p1);
            *(uint32_t*)(sm + (pb - sb) + off1) = pack_h2(p2, p3);
        }
#pragma unroll
        for (int j = 0; j < 8; j++) {
            o[j][0] *= f0; o[j][1] *= f0; o[j][2] *= f1; o[j][3] *= f1;
        }
        s0 += __shfl_xor_sync(0xffffffff, s0, 1);
        s0 += __shfl_xor_sync(0xffffffff, s0, 2);
        s1 += __shfl_xor_sync(0xffffffff, s1, 1);
        s1 += __shfl_xor_sync(0xffffffff, s1, 2);
        l0 = l0 * f0 + s0;
        l1 = l1 * f1 + s1;
        __syncwarp();      // P writes (warp-local rows) visible before ldsm

        // ---- O += P V (128-deep, 1-term) ----
#pragma unroll
        for (int ks = 0; ks < 8; ks++) {
            uint32_t pbase = (ks < 4) ? Pa : Pb;
            int ksl = ks & 3;
            uint32_t offp = sw128((uint32_t)(ar * 128 + (ksl * 16 + (lane >> 4) * 8) * 2));
            uint32_t ph4[4];
            ldsm4(pbase + offp, ph4);
            uint32_t vh4[4][4];
#pragma unroll
            for (int u = 0; u < 4; u++) {
                int vr = ks * 16 + ((lane >> 4) << 3) + (lane & 7);
                int vc = u * 16 + ((lane >> 3) & 1) * 8;
                uint32_t offv = sw128((uint32_t)(vr * 128 + vc * 2));
                ldsm4t(Vh + offv, vh4[u]);
            }
#pragma unroll
            for (int u = 0; u < 4; u++) {
                mma16816(o[2*u],   ph4, vh4[u][0], vh4[u][2]);
                mma16816(o[2*u+1], ph4, vh4[u][1], vh4[u][3]);
            }
        }
    }

    // ---- epilogue: normalize + write fp16 [B,N,E] ----
    float inv0 = 1.f / l0, inv1 = 1.f / l1;
    int b = bh >> 4, h = bh & 15;
#pragma unroll
    for (int j = 0; j < 8; j++) {
        int d = h * 64 + j * 8 + (lane & 3) * 2;
        size_t i0 = ((size_t)b * N_ + grow0) * E_ + d;
        size_t i1 = ((size_t)b * N_ + grow1) * E_ + d;
        *(uint32_t*)&g_at_hi[i0] = pack_h2(o[j][0] * inv0, o[j][1] * inv0);
        *(uint32_t*)&g_at_hi[i1] = pack_h2(o[j][2] * inv1, o[j][3] * inv1);
    }
}

// =====================================================================
// launch
// =====================================================================
extern "C" void kernel_launch(void* const* d_in, const int* in_sizes, int n_in,
                              void* d_out, int out_size)
{
    const float* x     = (const float*)d_in[0];
    const float* qkv_w = (const float*)d_in[1];
    const float* qkv_b = (const float*)d_in[2];
    const float* out_w = (const float*)d_in[3];
    const float* out_b = (const float*)d_in[4];
    float* out = (float*)d_out;

    const int M = B_ * N_;
    const int gemm_smem = 2 * GT_STAGE + 1024;   // 65 KB -> 2 CTAs/SM

    cudaFuncSetAttribute(gemm_mma<0>, cudaFuncAttributeMaxDynamicSharedMemorySize, gemm_smem);
    cudaFuncSetAttribute(gemm_mma<1>, cudaFuncAttributeMaxDynamicSharedMemorySize, gemm_smem);
    cudaFuncSetAttribute(attention_kernel, cudaFuncAttributeMaxDynamicSharedMemorySize, ATT_SMEM);

    // 1) one merged split launch (x, qkv_w, out_w -> fp16)
    {
        int total = X4_ + W4_ + OW4_;
        split_all<<<(total + 255) / 256, 256>>>(x, qkv_w, out_w);
    }

    // 2) QKV projection -> q/k/v fp16 [B,H,N,D]
    gemm_mma<0><<<dim3(3 * E_ / 128, M / 128), 256, gemm_smem>>>(qkv_b, nullptr, E_, 3 * E_);

    // 3) causal flash attention -> g_at_hi [B,N,E]
    attention_kernel<<<dim3(N_ / 64, B_ * H_), 128, ATT_SMEM>>>();

    // 4) output projection -> out (fp32)
    gemm_mma<1><<<dim3(E_ / 128, M / 128), 256, gemm_smem>>>(out_b, out, E_, E_);
}